// round 9
// baseline (speedup 1.0000x reference)
#include <cuda_runtime.h>
#include <math.h>
#include <stdint.h>

#define BB 16
#define NN 768
#define EE 1024
#define HH 16
#define DD 64
#define NEGV (-1e16f)

// Scratch (static device globals; no runtime allocation allowed).
// All values stored here are tf32-rounded (valid tf32 bit patterns in fp32).
__device__ float g_qh[BB * HH * NN * DD];   // (B,H,N,D), pre-scaled by 1/32
__device__ float g_kh[BB * HH * NN * DD];
__device__ float g_vh[BB * HH * NN * DD];
__device__ float g_attn[BB * NN * EE];      // (B,N,E) pre-final-projection
__device__ float g_wtf[EE * EE];            // tf32-rounded Wf

// ---------------------------------------------------------------------------
// helpers
// ---------------------------------------------------------------------------
__device__ __forceinline__ uint32_t f2tf(float x) {
    uint32_t r;
    asm("cvt.rna.tf32.f32 %0, %1;" : "=r"(r) : "f"(x));
    return r;
}
__device__ __forceinline__ float f2tf_f(float x) {
    return __uint_as_float(f2tf(x));
}
__device__ __forceinline__ void mma_tf32(float d[4],
                                         uint32_t a0, uint32_t a1, uint32_t a2, uint32_t a3,
                                         uint32_t b0, uint32_t b1) {
    asm volatile(
        "mma.sync.aligned.m16n8k8.row.col.f32.tf32.tf32.f32 "
        "{%0,%1,%2,%3}, {%4,%5,%6,%7}, {%8,%9}, {%0,%1,%2,%3};\n"
        : "+f"(d[0]), "+f"(d[1]), "+f"(d[2]), "+f"(d[3])
        : "r"(a0), "r"(a1), "r"(a2), "r"(a3), "r"(b0), "r"(b1));
}
#define LDSM4(r0, r1, r2, r3, addr) \
    asm volatile("ldmatrix.sync.aligned.m8n8.x4.shared.b16 {%0,%1,%2,%3}, [%4];" \
                 : "=r"(r0), "=r"(r1), "=r"(r2), "=r"(r3) : "r"(addr))

__device__ __forceinline__ void cp16(void* smem, const void* gmem) {
    uint32_t s = (uint32_t)__cvta_generic_to_shared(smem);
    asm volatile("cp.async.cg.shared.global [%0], [%1], 16;\n" :: "r"(s), "l"(gmem));
}
__device__ __forceinline__ void cp_commit() { asm volatile("cp.async.commit_group;\n"); }
__device__ __forceinline__ void cp_wait0() { asm volatile("cp.async.wait_group 0;\n"); }

// ---------------------------------------------------------------------------
// Stage A (merged): per-head projections via legacy tf32 mma + Wf tf32 prepass.
// grid (6, 256, 4), block 256.  (unchanged from the 603.9us run)
// smem (floats): Xs[128][76] | Ws[64][76]  = 58368 B
// ---------------------------------------------------------------------------
#define PXS(r, c_) sm[(r) * 76 + (c_)]
#define PWS(r, c_) sm[9728 + (r) * 76 + (c_)]

__global__ __launch_bounds__(256) void proj_mma_kernel(
    const float* __restrict__ q, const float* __restrict__ k, const float* __restrict__ v,
    const float* __restrict__ Wq, const float* __restrict__ Wk, const float* __restrict__ Wv,
    const float* __restrict__ Wf)
{
    extern __shared__ float sm[];
    const int which = blockIdx.z;
    const int tid = threadIdx.x;

    if (which == 3) {
        const int idx4 = (blockIdx.y * 6 + blockIdx.x) * 256 + tid;
        if (idx4 < EE * EE / 4) {
            float4 vv = *(const float4*)(Wf + idx4 * 4);
            *(float4*)(g_wtf + idx4 * 4) =
                make_float4(f2tf_f(vv.x), f2tf_f(vv.y), f2tf_f(vv.z), f2tf_f(vv.w));
        }
        return;
    }

    const float* X = (which == 0) ? q : (which == 1) ? k : v;
    const float* W = (which == 0) ? Wq : (which == 1) ? Wk : Wv;
    float* Y = (which == 0) ? g_qh : (which == 1) ? g_kh : g_vh;
    const float oscl = (which == 0) ? 0.03125f : 1.0f;

    const int bh = blockIdx.y;
    const int b = bh >> 4, h = bh & 15;
    const int n0 = blockIdx.x * 128;

    {
        const int rr = tid >> 4;
        const int c4 = (tid & 15) * 4;
        const float* src = X + ((size_t)b * NN + n0) * EE + h * DD;
        #pragma unroll
        for (int i = 0; i < 8; i++) {
            const int row = rr + 16 * i;
            float4 vv = *(const float4*)(src + (size_t)row * EE + c4);
            *(float4*)&PXS(row, c4) =
                make_float4(f2tf_f(vv.x), f2tf_f(vv.y), f2tf_f(vv.z), f2tf_f(vv.w));
        }
        const float* wsrc = W + h * DD * DD;
        #pragma unroll
        for (int i = 0; i < 4; i++) {
            const int row = rr + 16 * i;
            float4 wv = *(const float4*)(wsrc + row * DD + c4);
            *(float4*)&PWS(row, c4) =
                make_float4(f2tf_f(wv.x), f2tf_f(wv.y), f2tf_f(wv.z), f2tf_f(wv.w));
        }
    }
    __syncthreads();

    const int w = tid >> 5;
    const int lane = tid & 31;
    const int g = lane >> 2;
    const int qd = lane & 3;
    const int qrow = 16 * w + g;

    float acc[8][4] = {};
    #pragma unroll
    for (int kk = 0; kk < 8; kk++) {
        uint32_t a0 = __float_as_uint(PXS(qrow,     kk * 8 + qd));
        uint32_t a1 = __float_as_uint(PXS(qrow + 8, kk * 8 + qd));
        uint32_t a2 = __float_as_uint(PXS(qrow,     kk * 8 + qd + 4));
        uint32_t a3 = __float_as_uint(PXS(qrow + 8, kk * 8 + qd + 4));
        #pragma unroll
        for (int nt = 0; nt < 8; nt++) {
            uint32_t b0 = __float_as_uint(PWS(nt * 8 + g, kk * 8 + qd));
            uint32_t b1 = __float_as_uint(PWS(nt * 8 + g, kk * 8 + qd + 4));
            mma_tf32(acc[nt], a0, a1, a2, a3, b0, b1);
        }
    }

    float* dst = Y + (((size_t)bh) * NN + n0 + 16 * w) * DD;
    #pragma unroll
    for (int nt = 0; nt < 8; nt++) {
        const int col = nt * 8 + 2 * qd;
        *(float2*)(dst + (size_t)g * DD + col) =
            make_float2(f2tf_f(acc[nt][0] * oscl), f2tf_f(acc[nt][1] * oscl));
        *(float2*)(dst + (size_t)(g + 8) * DD + col) =
            make_float2(f2tf_f(acc[nt][2] * oscl), f2tf_f(acc[nt][3] * oscl));
    }
}

// ---------------------------------------------------------------------------
// Stage B: flash attention, ktile=64, sync K/V staging (R7 structure),
// ldmatrix fragment loads; V staged TRANSPOSED for LDSM B-fragments.
// grid (6, 256), block 256, dynamic smem 80896 B, 2 CTAs/SM.
// smem (floats): Qs[128][76] | K[64][76] | VT[64][76] | madd[768]
// ---------------------------------------------------------------------------
#define QS(r, c_)  sm[(r) * 76 + (c_)]
#define KS(r, c_)  sm[9728 + (r) * 76 + (c_)]
#define VT(r, c_)  sm[14592 + (r) * 76 + (c_)]
#define MADD(i)    sm[19456 + (i)]

__global__ __launch_bounds__(256, 2) void attn_tf32_kernel(const float* __restrict__ mask)
{
    extern __shared__ float sm[];

    const int bh = blockIdx.y;
    const int b = bh >> 4, h = bh & 15;
    const int q0 = blockIdx.x * 128;
    const int tid = threadIdx.x;
    const int w = tid >> 5;
    const int lane = tid & 31;
    const int g = lane >> 2;
    const int qd = lane & 3;

    for (int i = tid; i < NN; i += 256)
        MADD(i) = (mask[h * NN + i] == -INFINITY) ? NEGV : 0.f;

    const float* qb = g_qh + ((size_t)bh * NN + q0) * DD;
    {
        const int rr = tid >> 4, c4 = (tid & 15) * 4;
        #pragma unroll
        for (int i = 0; i < 8; i++)
            *(float4*)&QS(rr + 16 * i, c4) =
                *(const float4*)(qb + (size_t)(rr + 16 * i) * DD + c4);
    }
    __syncthreads();

    const int qrow = 16 * w + g;
    const float addq0 = MADD(q0 + qrow);
    const float addq1 = MADD(q0 + qrow + 8);

    float m0r = -INFINITY, m1r = -INFINITY, l0 = 0.f, l1 = 0.f;
    float o[8][4] = {};

    const float* kb = g_kh + ((size_t)bh * NN) * DD;
    const float* vb = g_vh + ((size_t)bh * NN) * DD;

    const int shbase = lane & ~3;
    const int s0l = shbase + (qd >> 1);
    const int s2l = shbase + (qd >> 1) + 2;
    const bool odd = qd & 1;

    // ldmatrix address bases (byte addresses into shared)
    const uint32_t smb = (uint32_t)__cvta_generic_to_shared(sm);
    const int sq = lane >> 3, rp = lane & 7;
    const uint32_t aQ = smb + 4u * ((16 * w + (sq & 1) * 8 + rp) * 76 + (sq >> 1) * 4);
    uint32_t aK[4], aV[4];
    #pragma unroll
    for (int p = 0; p < 4; p++) {
        aK[p] = smb + 4u * (9728  + (p * 16 + (sq >> 1) * 8 + rp) * 76 + (sq & 1) * 4);
        aV[p] = smb + 4u * (14592 + (p * 16 + (sq >> 1) * 8 + rp) * 76 + (sq & 1) * 4);
    }

    // V transpose staging map: lane-consecutive rows -> conflict-free STS
    const int vr = tid & 63;            // source k-row within tile
    const int vc0 = (tid >> 6) * 16;    // source d-col base

    for (int kt = 0; kt < NN; kt += 64) {
        __syncthreads();
        {
            const int rr = tid >> 4, c4 = (tid & 15) * 4;
            #pragma unroll
            for (int i = 0; i < 4; i++)
                *(float4*)&KS(rr + 16 * i, c4) =
                    *(const float4*)(kb + (size_t)(kt + rr + 16 * i) * DD + c4);
            #pragma unroll
            for (int i = 0; i < 4; i++) {
                float4 vv = *(const float4*)(vb + (size_t)(kt + vr) * DD + vc0 + 4 * i);
                VT(vc0 + 4 * i + 0, vr) = vv.x;
                VT(vc0 + 4 * i + 1, vr) = vv.y;
                VT(vc0 + 4 * i + 2, vr) = vv.z;
                VT(vc0 + 4 * i + 3, vr) = vv.w;
            }
        }
        __syncthreads();

        // S = Q K^T  (LDSM fragment feeds)
        float s[8][4] = {};
        #pragma unroll
        for (int kk = 0; kk < 8; kk++) {
            uint32_t a0, a1, a2, a3;
            LDSM4(a0, a1, a2, a3, aQ + kk * 32);
            #pragma unroll
            for (int p = 0; p < 4; p++) {
                uint32_t b0, b1, b2, b3;
                LDSM4(b0, b1, b2, b3, aK[p] + kk * 32);
                mma_tf32(s[2 * p],     a0, a1, a2, a3, b0, b1);
                mma_tf32(s[2 * p + 1], a0, a1, a2, a3, b2, b3);
            }
        }

        float pm0 = -INFINITY, pm1 = -INFINITY;
        #pragma unroll
        for (int nt = 0; nt < 8; nt++) {
            float2 mk = *(const float2*)&MADD(kt + nt * 8 + 2 * qd);
            s[nt][0] += fmaxf(addq0 + mk.x, NEGV);
            s[nt][1] += fmaxf(addq0 + mk.y, NEGV);
            s[nt][2] += fmaxf(addq1 + mk.x, NEGV);
            s[nt][3] += fmaxf(addq1 + mk.y, NEGV);
            pm0 = fmaxf(pm0, fmaxf(s[nt][0], s[nt][1]));
            pm1 = fmaxf(pm1, fmaxf(s[nt][2], s[nt][3]));
        }
        pm0 = fmaxf(pm0, __shfl_xor_sync(0xffffffffu, pm0, 1));
        pm0 = fmaxf(pm0, __shfl_xor_sync(0xffffffffu, pm0, 2));
        pm1 = fmaxf(pm1, __shfl_xor_sync(0xffffffffu, pm1, 1));
        pm1 = fmaxf(pm1, __shfl_xor_sync(0xffffffffu, pm1, 2));

        const float mn0 = fmaxf(m0r, pm0), mn1 = fmaxf(m1r, pm1);
        const float corr0 = __expf(m0r - mn0), corr1 = __expf(m1r - mn1);
        m0r = mn0; m1r = mn1;

        float rs0 = 0.f, rs1 = 0.f;
        #pragma unroll
        for (int nt = 0; nt < 8; nt++) {
            s[nt][0] = __expf(s[nt][0] - mn0); rs0 += s[nt][0];
            s[nt][1] = __expf(s[nt][1] - mn0); rs0 += s[nt][1];
            s[nt][2] = __expf(s[nt][2] - mn1); rs1 += s[nt][2];
            s[nt][3] = __expf(s[nt][3] - mn1); rs1 += s[nt][3];
        }
        rs0 += __shfl_xor_sync(0xffffffffu, rs0, 1);
        rs0 += __shfl_xor_sync(0xffffffffu, rs0, 2);
        rs1 += __shfl_xor_sync(0xffffffffu, rs1, 1);
        rs1 += __shfl_xor_sync(0xffffffffu, rs1, 2);
        l0 = l0 * corr0 + rs0;
        l1 = l1 * corr1 + rs1;

        #pragma unroll
        for (int dt = 0; dt < 8; dt++) {
            o[dt][0] *= corr0; o[dt][1] *= corr0;
            o[dt][2] *= corr1; o[dt][3] *= corr1;
        }

        // O += P V  (A from shuffles; V B-frags via LDSM on transposed tile)
        #pragma unroll
        for (int kk = 0; kk < 8; kk++) {
            float e0 = __shfl_sync(0xffffffffu, s[kk][0], s0l);
            float e1 = __shfl_sync(0xffffffffu, s[kk][1], s0l);
            float e2 = __shfl_sync(0xffffffffu, s[kk][2], s0l);
            float e3 = __shfl_sync(0xffffffffu, s[kk][3], s0l);
            float f0 = __shfl_sync(0xffffffffu, s[kk][0], s2l);
            float f1 = __shfl_sync(0xffffffffu, s[kk][1], s2l);
            float f2 = __shfl_sync(0xffffffffu, s[kk][2], s2l);
            float f3 = __shfl_sync(0xffffffffu, s[kk][3], s2l);
            uint32_t a0 = f2tf(odd ? e1 : e0);
            uint32_t a1 = f2tf(odd ? e3 : e2);
            uint32_t a2 = f2tf(odd ? f1 : f0);
            uint32_t a3 = f2tf(odd ? f3 : f2);
            #pragma unroll
            for (int p = 0; p < 4; p++) {
                uint32_t b0, b1, b2, b3;
                LDSM4(b0, b1, b2, b3, aV[p] + kk * 32);
                mma_tf32(o[2 * p],     a0, a1, a2, a3, b0, b1);
                mma_tf32(o[2 * p + 1], a0, a1, a2, a3, b2, b3);
            }
        }
    }

    const float inv0 = 1.f / l0, inv1 = 1.f / l1;
    float* ob = g_attn + ((size_t)b * NN + q0 + 16 * w) * EE + h * DD;
    #pragma unroll
    for (int dt = 0; dt < 8; dt++) {
        float2 v0 = make_float2(f2tf_f(o[dt][0] * inv0), f2tf_f(o[dt][1] * inv0));
        float2 v1 = make_float2(f2tf_f(o[dt][2] * inv1), f2tf_f(o[dt][3] * inv1));
        *(float2*)(ob + (size_t)g * EE + dt * 8 + 2 * qd) = v0;
        *(float2*)(ob + (size_t)(g + 8) * EE + dt * 8 + 2 * qd) = v1;
    }
}

// ---------------------------------------------------------------------------
// Stage C: out = g_attn @ Wf^T, tf32 mma, 128x128x32 cp.async pipeline,
// LDSM fragment feeds. grid (8, 96), block 256, smem 73728 B.
// smem: As[2][128][36] | Ws[2][128][36]
// ---------------------------------------------------------------------------
#define GAS(bf, r, c_) sm[(bf) * 4608 + (r) * 36 + (c_)]
#define GWS(bf, r, c_) sm[9216 + (bf) * 4608 + (r) * 36 + (c_)]

__global__ __launch_bounds__(256, 2) void gemm_tf32_kernel(float* __restrict__ out)
{
    extern __shared__ float sm[];

    const int e0 = blockIdx.x * 128;
    const int m0 = blockIdx.y * 128;
    const int tid = threadIdx.x;
    const int w = tid >> 5;
    const int lane = tid & 31;
    const int g = lane >> 2, qd = lane & 3;
    const int mb = (w & 1) * 64;
    const int nb = (w >> 1) * 32;

    const float* Ab = g_attn + (size_t)m0 * EE;
    const float* Wb = g_wtf + (size_t)e0 * EE;

    const int rr = tid >> 3;           // 0..31
    const int c4 = (tid & 7) * 4;      // 0..28

    // ldmatrix address bases (buffer 0); buffer stride = 18432 bytes
    const uint32_t smb = (uint32_t)__cvta_generic_to_shared(sm);
    const int sq = lane >> 3, rp = lane & 7;
    uint32_t aA[4], aB[2];
    #pragma unroll
    for (int mt = 0; mt < 4; mt++)
        aA[mt] = smb + 4u * ((mb + mt * 16 + (sq & 1) * 8 + rp) * 36 + (sq >> 1) * 4);
    #pragma unroll
    for (int p = 0; p < 2; p++)
        aB[p] = smb + 4u * (9216 + (nb + p * 16 + (sq >> 1) * 8 + rp) * 36 + (sq & 1) * 4);

    float acc[4][4][4] = {};

    #pragma unroll
    for (int i = 0; i < 4; i++) {
        cp16(&GAS(0, rr + 32 * i, c4), Ab + (size_t)(rr + 32 * i) * EE + c4);
        cp16(&GWS(0, rr + 32 * i, c4), Wb + (size_t)(rr + 32 * i) * EE + c4);
    }
    cp_commit();

    for (int it = 0; it < EE / 32; it++) {
        const int buf = it & 1;
        const uint32_t boff = buf * 18432u;
        cp_wait0();
        __syncthreads();

        if (it + 1 < EE / 32) {
            const int kc = (it + 1) * 32;
            #pragma unroll
            for (int i = 0; i < 4; i++) {
                cp16(&GAS(buf ^ 1, rr + 32 * i, c4),
                     Ab + (size_t)(rr + 32 * i) * EE + kc + c4);
                cp16(&GWS(buf ^ 1, rr + 32 * i, c4),
                     Wb + (size_t)(rr + 32 * i) * EE + kc + c4);
            }
            cp_commit();
        }

        #pragma unroll
        for (int kk = 0; kk < 4; kk++) {
            uint32_t a[4][4];
            #pragma unroll
            for (int mt = 0; mt < 4; mt++)
                LDSM4(a[mt][0], a[mt][1], a[mt][2], a[mt][3], aA[mt] + boff + kk * 32);
            #pragma unroll
            for (int p = 0; p < 2; p++) {
                uint32_t b0, b1, b2, b3;
                LDSM4(b0, b1, b2, b3, aB[p] + boff + kk * 32);
                #pragma unroll
                for (int mt = 0; mt < 4; mt++) {
                    mma_tf32(acc[mt][2 * p],     a[mt][0], a[mt][1], a[mt][2], a[mt][3], b0, b1);
                    mma_tf32(acc[mt][2 * p + 1], a[mt][0], a[mt][1], a[mt][2], a[mt][3], b2, b3);
                }
            }
        }
    }

    #pragma unroll
    for (int mt = 0; mt < 4; mt++) {
        const int row0 = m0 + mb + mt * 16 + g;
        #pragma unroll
        for (int nt = 0; nt < 4; nt++) {
            const int col = e0 + nb + nt * 8 + 2 * qd;
            *(float2*)(out + (size_t)row0 * EE + col) =
                make_float2(acc[mt][nt][0], acc[mt][nt][1]);
            *(float2*)(out + (size_t)(row0 + 8) * EE + col) =
                make_float2(acc[mt][nt][2], acc[mt][nt][3]);
        }
    }
}

// ---------------------------------------------------------------------------
extern "C" void kernel_launch(void* const* d_in, const int* in_sizes, int n_in,
                              void* d_out, int out_size)
{
    const float* q    = (const float*)d_in[0];
    const float* k    = (const float*)d_in[1];
    const float* v    = (const float*)d_in[2];
    const float* mask = (const float*)d_in[3];
    const float* Wq   = (const float*)d_in[4];
    const float* Wk   = (const float*)d_in[5];
    const float* Wv   = (const float*)d_in[6];
    const float* Wf   = (const float*)d_in[7];
    float* out = (float*)d_out;

    const int proj_smem = (128 * 76 + 64 * 76) * (int)sizeof(float);  // 58368
    const int attn_smem = 20224 * (int)sizeof(float);                 // 80896
    const int gemm_smem = 18432 * (int)sizeof(float);                 // 73728
    cudaFuncSetAttribute(proj_mma_kernel,
                         cudaFuncAttributeMaxDynamicSharedMemorySize, proj_smem);
    cudaFuncSetAttribute(attn_tf32_kernel,
                         cudaFuncAttributeMaxDynamicSharedMemorySize, attn_smem);
    cudaFuncSetAttribute(gemm_tf32_kernel,
                         cudaFuncAttributeMaxDynamicSharedMemorySize, gemm_smem);

    proj_mma_kernel<<<dim3(NN / 128, BB * HH, 4), 256, proj_smem>>>(
        q, k, v, Wq, Wk, Wv, Wf);
    attn_tf32_kernel<<<dim3(NN / 128, BB * HH), 256, attn_smem>>>(mask);
    gemm_tf32_kernel<<<dim3(EE / 128, (BB * NN) / 128), 256, gemm_smem>>>(out);
}

// round 10
// speedup vs baseline: 1.0309x; 1.0309x over previous
#include <cuda_runtime.h>
#include <math.h>
#include <stdint.h>

#define BB 16
#define NN 768
#define EE 1024
#define HH 16
#define DD 64
// mask addend in log2 domain: -1e16 * log2(e)
#define NEGV2 (-1.4426950e16f)

// Scratch (static device globals; no runtime allocation allowed).
// All values stored here are tf32-rounded (valid tf32 bit patterns in fp32).
__device__ float g_qh[BB * HH * NN * DD];   // (B,H,N,D), pre-scaled by log2e/32
__device__ float g_kh[BB * HH * NN * DD];
__device__ float g_vh[BB * HH * NN * DD];
__device__ float g_attn[BB * NN * EE];      // (B,N,E) pre-final-projection
__device__ float g_wtf[EE * EE];            // tf32-rounded Wf

// ---------------------------------------------------------------------------
// helpers
// ---------------------------------------------------------------------------
__device__ __forceinline__ uint32_t f2tf(float x) {
    uint32_t r;
    asm("cvt.rna.tf32.f32 %0, %1;" : "=r"(r) : "f"(x));
    return r;
}
__device__ __forceinline__ float f2tf_f(float x) {
    return __uint_as_float(f2tf(x));
}
__device__ __forceinline__ float ex2(float x) {
    float y;
    asm("ex2.approx.f32 %0, %1;" : "=f"(y) : "f"(x));
    return y;
}
__device__ __forceinline__ void mma_tf32(float d[4],
                                         uint32_t a0, uint32_t a1, uint32_t a2, uint32_t a3,
                                         uint32_t b0, uint32_t b1) {
    asm volatile(
        "mma.sync.aligned.m16n8k8.row.col.f32.tf32.tf32.f32 "
        "{%0,%1,%2,%3}, {%4,%5,%6,%7}, {%8,%9}, {%0,%1,%2,%3};\n"
        : "+f"(d[0]), "+f"(d[1]), "+f"(d[2]), "+f"(d[3])
        : "r"(a0), "r"(a1), "r"(a2), "r"(a3), "r"(b0), "r"(b1));
}
__device__ __forceinline__ void cp16(void* smem, const void* gmem) {
    uint32_t s = (uint32_t)__cvta_generic_to_shared(smem);
    asm volatile("cp.async.cg.shared.global [%0], [%1], 16;\n" :: "r"(s), "l"(gmem));
}
__device__ __forceinline__ void cp_commit() { asm volatile("cp.async.commit_group;\n"); }
__device__ __forceinline__ void cp_wait0() { asm volatile("cp.async.wait_group 0;\n"); }

// ---------------------------------------------------------------------------
// Stage A (merged): per-head projections via legacy tf32 mma + Wf tf32 prepass.
// grid (6, 256, 4), block 256.
// Q output scaled by log2e/sqrt(E) so attn softmax uses raw ex2.
// smem (floats): Xs[128][76] | Ws[64][76]  = 58368 B
// ---------------------------------------------------------------------------
#define PXS(r, c_) sm[(r) * 76 + (c_)]
#define PWS(r, c_) sm[9728 + (r) * 76 + (c_)]

__global__ __launch_bounds__(256) void proj_mma_kernel(
    const float* __restrict__ q, const float* __restrict__ k, const float* __restrict__ v,
    const float* __restrict__ Wq, const float* __restrict__ Wk, const float* __restrict__ Wv,
    const float* __restrict__ Wf)
{
    extern __shared__ float sm[];
    const int which = blockIdx.z;
    const int tid = threadIdx.x;

    if (which == 3) {
        const int idx4 = (blockIdx.y * 6 + blockIdx.x) * 256 + tid;
        if (idx4 < EE * EE / 4) {
            float4 vv = *(const float4*)(Wf + idx4 * 4);
            *(float4*)(g_wtf + idx4 * 4) =
                make_float4(f2tf_f(vv.x), f2tf_f(vv.y), f2tf_f(vv.z), f2tf_f(vv.w));
        }
        return;
    }

    const float* X = (which == 0) ? q : (which == 1) ? k : v;
    const float* W = (which == 0) ? Wq : (which == 1) ? Wk : Wv;
    float* Y = (which == 0) ? g_qh : (which == 1) ? g_kh : g_vh;
    const float oscl = (which == 0) ? (0.03125f * 1.44269504f) : 1.0f;

    const int bh = blockIdx.y;
    const int b = bh >> 4, h = bh & 15;
    const int n0 = blockIdx.x * 128;

    {
        const int rr = tid >> 4;
        const int c4 = (tid & 15) * 4;
        const float* src = X + ((size_t)b * NN + n0) * EE + h * DD;
        #pragma unroll
        for (int i = 0; i < 8; i++) {
            const int row = rr + 16 * i;
            float4 vv = *(const float4*)(src + (size_t)row * EE + c4);
            *(float4*)&PXS(row, c4) =
                make_float4(f2tf_f(vv.x), f2tf_f(vv.y), f2tf_f(vv.z), f2tf_f(vv.w));
        }
        const float* wsrc = W + h * DD * DD;
        #pragma unroll
        for (int i = 0; i < 4; i++) {
            const int row = rr + 16 * i;
            float4 wv = *(const float4*)(wsrc + row * DD + c4);
            *(float4*)&PWS(row, c4) =
                make_float4(f2tf_f(wv.x), f2tf_f(wv.y), f2tf_f(wv.z), f2tf_f(wv.w));
        }
    }
    __syncthreads();

    const int w = tid >> 5;
    const int lane = tid & 31;
    const int g = lane >> 2;
    const int qd = lane & 3;
    const int qrow = 16 * w + g;

    float acc[8][4] = {};
    #pragma unroll
    for (int kk = 0; kk < 8; kk++) {
        uint32_t a0 = __float_as_uint(PXS(qrow,     kk * 8 + qd));
        uint32_t a1 = __float_as_uint(PXS(qrow + 8, kk * 8 + qd));
        uint32_t a2 = __float_as_uint(PXS(qrow,     kk * 8 + qd + 4));
        uint32_t a3 = __float_as_uint(PXS(qrow + 8, kk * 8 + qd + 4));
        #pragma unroll
        for (int nt = 0; nt < 8; nt++) {
            uint32_t b0 = __float_as_uint(PWS(nt * 8 + g, kk * 8 + qd));
            uint32_t b1 = __float_as_uint(PWS(nt * 8 + g, kk * 8 + qd + 4));
            mma_tf32(acc[nt], a0, a1, a2, a3, b0, b1);
        }
    }

    float* dst = Y + (((size_t)bh) * NN + n0 + 16 * w) * DD;
    #pragma unroll
    for (int nt = 0; nt < 8; nt++) {
        const int col = nt * 8 + 2 * qd;
        *(float2*)(dst + (size_t)g * DD + col) =
            make_float2(f2tf_f(acc[nt][0] * oscl), f2tf_f(acc[nt][1] * oscl));
        *(float2*)(dst + (size_t)(g + 8) * DD + col) =
            make_float2(f2tf_f(acc[nt][2] * oscl), f2tf_f(acc[nt][3] * oscl));
    }
}

// ---------------------------------------------------------------------------
// Stage B: flash attention (R7 structure: ktile=64, sync staging, MADD table),
// log2-domain softmax with raw ex2.
// grid (6, 256), block 256, dynamic smem 79872 B, 2 CTAs/SM.
// smem (floats): Qs[128][76] | Ks[64][76] | Vs[64][72] | madd[768]
// ---------------------------------------------------------------------------
#define QS(r, c_) sm[(r) * 76 + (c_)]
#define KS(r, c_) sm[9728 + (r) * 76 + (c_)]
#define VS(r, c_) sm[14592 + (r) * 72 + (c_)]
#define MADD(i)   sm[19200 + (i)]

__global__ __launch_bounds__(256, 2) void attn_tf32_kernel(const float* __restrict__ mask)
{
    extern __shared__ float sm[];

    const int bh = blockIdx.y;
    const int b = bh >> 4, h = bh & 15;
    const int q0 = blockIdx.x * 128;
    const int tid = threadIdx.x;
    const int w = tid >> 5;
    const int lane = tid & 31;
    const int g = lane >> 2;
    const int qd = lane & 3;

    for (int i = tid; i < NN; i += 256)
        MADD(i) = (mask[h * NN + i] == -INFINITY) ? NEGV2 : 0.f;

    const float* qb = g_qh + ((size_t)bh * NN + q0) * DD;
    {
        const int rr = tid >> 4, c4 = (tid & 15) * 4;
        #pragma unroll
        for (int i = 0; i < 8; i++)
            *(float4*)&QS(rr + 16 * i, c4) =
                *(const float4*)(qb + (size_t)(rr + 16 * i) * DD + c4);
    }
    __syncthreads();

    const int qrow = 16 * w + g;
    const float addq0 = MADD(q0 + qrow);
    const float addq1 = MADD(q0 + qrow + 8);

    float m0r = -INFINITY, m1r = -INFINITY, l0 = 0.f, l1 = 0.f;
    float o[8][4] = {};

    const float* kb = g_kh + ((size_t)bh * NN) * DD;
    const float* vb = g_vh + ((size_t)bh * NN) * DD;

    const int shbase = lane & ~3;
    const int s0l = shbase + (qd >> 1);
    const int s2l = shbase + (qd >> 1) + 2;
    const bool odd = qd & 1;

    for (int kt = 0; kt < NN; kt += 64) {
        __syncthreads();
        {
            const int rr = tid >> 4, c4 = (tid & 15) * 4;
            #pragma unroll
            for (int i = 0; i < 4; i++) {
                *(float4*)&KS(rr + 16 * i, c4) =
                    *(const float4*)(kb + (size_t)(kt + rr + 16 * i) * DD + c4);
                *(float4*)&VS(rr + 16 * i, c4) =
                    *(const float4*)(vb + (size_t)(kt + rr + 16 * i) * DD + c4);
            }
        }
        __syncthreads();

        float s[8][4] = {};
        #pragma unroll
        for (int kk = 0; kk < 8; kk++) {
            uint32_t a0 = __float_as_uint(QS(qrow,     kk * 8 + qd));
            uint32_t a1 = __float_as_uint(QS(qrow + 8, kk * 8 + qd));
            uint32_t a2 = __float_as_uint(QS(qrow,     kk * 8 + qd + 4));
            uint32_t a3 = __float_as_uint(QS(qrow + 8, kk * 8 + qd + 4));
            #pragma unroll
            for (int nt = 0; nt < 8; nt++) {
                uint32_t b0 = __float_as_uint(KS(nt * 8 + g, kk * 8 + qd));
                uint32_t b1 = __float_as_uint(KS(nt * 8 + g, kk * 8 + qd + 4));
                mma_tf32(s[nt], a0, a1, a2, a3, b0, b1);
            }
        }

        float pm0 = -INFINITY, pm1 = -INFINITY;
        #pragma unroll
        for (int nt = 0; nt < 8; nt++) {
            float2 mk = *(const float2*)&MADD(kt + nt * 8 + 2 * qd);
            s[nt][0] += fmaxf(addq0 + mk.x, NEGV2);
            s[nt][1] += fmaxf(addq0 + mk.y, NEGV2);
            s[nt][2] += fmaxf(addq1 + mk.x, NEGV2);
            s[nt][3] += fmaxf(addq1 + mk.y, NEGV2);
            pm0 = fmaxf(pm0, fmaxf(s[nt][0], s[nt][1]));
            pm1 = fmaxf(pm1, fmaxf(s[nt][2], s[nt][3]));
        }
        pm0 = fmaxf(pm0, __shfl_xor_sync(0xffffffffu, pm0, 1));
        pm0 = fmaxf(pm0, __shfl_xor_sync(0xffffffffu, pm0, 2));
        pm1 = fmaxf(pm1, __shfl_xor_sync(0xffffffffu, pm1, 1));
        pm1 = fmaxf(pm1, __shfl_xor_sync(0xffffffffu, pm1, 2));

        const float mn0 = fmaxf(m0r, pm0), mn1 = fmaxf(m1r, pm1);
        const float corr0 = ex2(m0r - mn0), corr1 = ex2(m1r - mn1);
        m0r = mn0; m1r = mn1;

        float rs0 = 0.f, rs1 = 0.f;
        #pragma unroll
        for (int nt = 0; nt < 8; nt++) {
            s[nt][0] = ex2(s[nt][0] - mn0); rs0 += s[nt][0];
            s[nt][1] = ex2(s[nt][1] - mn0); rs0 += s[nt][1];
            s[nt][2] = ex2(s[nt][2] - mn1); rs1 += s[nt][2];
            s[nt][3] = ex2(s[nt][3] - mn1); rs1 += s[nt][3];
        }
        rs0 += __shfl_xor_sync(0xffffffffu, rs0, 1);
        rs0 += __shfl_xor_sync(0xffffffffu, rs0, 2);
        rs1 += __shfl_xor_sync(0xffffffffu, rs1, 1);
        rs1 += __shfl_xor_sync(0xffffffffu, rs1, 2);
        l0 = l0 * corr0 + rs0;
        l1 = l1 * corr1 + rs1;

        #pragma unroll
        for (int dt = 0; dt < 8; dt++) {
            o[dt][0] *= corr0; o[dt][1] *= corr0;
            o[dt][2] *= corr1; o[dt][3] *= corr1;
        }

        #pragma unroll
        for (int kk = 0; kk < 8; kk++) {
            float e0 = __shfl_sync(0xffffffffu, s[kk][0], s0l);
            float e1 = __shfl_sync(0xffffffffu, s[kk][1], s0l);
            float e2 = __shfl_sync(0xffffffffu, s[kk][2], s0l);
            float e3 = __shfl_sync(0xffffffffu, s[kk][3], s0l);
            float f0 = __shfl_sync(0xffffffffu, s[kk][0], s2l);
            float f1 = __shfl_sync(0xffffffffu, s[kk][1], s2l);
            float f2 = __shfl_sync(0xffffffffu, s[kk][2], s2l);
            float f3 = __shfl_sync(0xffffffffu, s[kk][3], s2l);
            uint32_t a0 = f2tf(odd ? e1 : e0);
            uint32_t a1 = f2tf(odd ? e3 : e2);
            uint32_t a2 = f2tf(odd ? f1 : f0);
            uint32_t a3 = f2tf(odd ? f3 : f2);
            #pragma unroll
            for (int dt = 0; dt < 8; dt++) {
                uint32_t b0 = __float_as_uint(VS(kk * 8 + qd,     dt * 8 + g));
                uint32_t b1 = __float_as_uint(VS(kk * 8 + qd + 4, dt * 8 + g));
                mma_tf32(o[dt], a0, a1, a2, a3, b0, b1);
            }
        }
    }

    const float inv0 = 1.f / l0, inv1 = 1.f / l1;
    float* ob = g_attn + ((size_t)b * NN + q0 + 16 * w) * EE + h * DD;
    #pragma unroll
    for (int dt = 0; dt < 8; dt++) {
        float2 v0 = make_float2(f2tf_f(o[dt][0] * inv0), f2tf_f(o[dt][1] * inv0));
        float2 v1 = make_float2(f2tf_f(o[dt][2] * inv1), f2tf_f(o[dt][3] * inv1));
        *(float2*)(ob + (size_t)g * EE + dt * 8 + 2 * qd) = v0;
        *(float2*)(ob + (size_t)(g + 8) * EE + dt * 8 + 2 * qd) = v1;
    }
}

// ---------------------------------------------------------------------------
// Stage C: out = g_attn @ Wf^T, tf32 mma. 128x128x32, 2-stage single-barrier
// cp.async pipeline (R3/R7 version). grid (8, 96), block 256, smem 73728 B.
// smem: As[2][128][36] | Ws[2][128][36]
// ---------------------------------------------------------------------------
#define GAS(bf, r, c_) sm[(bf) * 4608 + (r) * 36 + (c_)]
#define GWS(bf, r, c_) sm[9216 + (bf) * 4608 + (r) * 36 + (c_)]

__global__ __launch_bounds__(256, 2) void gemm_tf32_kernel(float* __restrict__ out)
{
    extern __shared__ float sm[];

    const int e0 = blockIdx.x * 128;
    const int m0 = blockIdx.y * 128;
    const int tid = threadIdx.x;
    const int w = tid >> 5;
    const int lane = tid & 31;
    const int g = lane >> 2, qd = lane & 3;
    const int mb = (w & 1) * 64;
    const int nb = (w >> 1) * 32;

    const float* Ab = g_attn + (size_t)m0 * EE;
    const float* Wb = g_wtf + (size_t)e0 * EE;

    const int rr = tid >> 3;           // 0..31
    const int c4 = (tid & 7) * 4;      // 0..28

    float acc[4][4][4] = {};

    #pragma unroll
    for (int i = 0; i < 4; i++) {
        cp16(&GAS(0, rr + 32 * i, c4), Ab + (size_t)(rr + 32 * i) * EE + c4);
        cp16(&GWS(0, rr + 32 * i, c4), Wb + (size_t)(rr + 32 * i) * EE + c4);
    }
    cp_commit();

    for (int it = 0; it < EE / 32; it++) {
        const int buf = it & 1;
        cp_wait0();
        __syncthreads();

        if (it + 1 < EE / 32) {
            const int kc = (it + 1) * 32;
            #pragma unroll
            for (int i = 0; i < 4; i++) {
                cp16(&GAS(buf ^ 1, rr + 32 * i, c4),
                     Ab + (size_t)(rr + 32 * i) * EE + kc + c4);
                cp16(&GWS(buf ^ 1, rr + 32 * i, c4),
                     Wb + (size_t)(rr + 32 * i) * EE + kc + c4);
            }
            cp_commit();
        }

        #pragma unroll
        for (int kk = 0; kk < 4; kk++) {
            uint32_t a[4][4];
            #pragma unroll
            for (int mt = 0; mt < 4; mt++) {
                const int row = mb + mt * 16 + g;
                a[mt][0] = __float_as_uint(GAS(buf, row,     kk * 8 + qd));
                a[mt][1] = __float_as_uint(GAS(buf, row + 8, kk * 8 + qd));
                a[mt][2] = __float_as_uint(GAS(buf, row,     kk * 8 + qd + 4));
                a[mt][3] = __float_as_uint(GAS(buf, row + 8, kk * 8 + qd + 4));
            }
            #pragma unroll
            for (int nt = 0; nt < 4; nt++) {
                uint32_t b0 = __float_as_uint(GWS(buf, nb + nt * 8 + g, kk * 8 + qd));
                uint32_t b1 = __float_as_uint(GWS(buf, nb + nt * 8 + g, kk * 8 + qd + 4));
                #pragma unroll
                for (int mt = 0; mt < 4; mt++)
                    mma_tf32(acc[mt][nt], a[mt][0], a[mt][1], a[mt][2], a[mt][3], b0, b1);
            }
        }
    }

    #pragma unroll
    for (int mt = 0; mt < 4; mt++) {
        const int row0 = m0 + mb + mt * 16 + g;
        #pragma unroll
        for (int nt = 0; nt < 4; nt++) {
            const int col = e0 + nb + nt * 8 + 2 * qd;
            *(float2*)(out + (size_t)row0 * EE + col) =
                make_float2(acc[mt][nt][0], acc[mt][nt][1]);
            *(float2*)(out + (size_t)(row0 + 8) * EE + col) =
                make_float2(acc[mt][nt][2], acc[mt][nt][3]);
        }
    }
}

// ---------------------------------------------------------------------------
extern "C" void kernel_launch(void* const* d_in, const int* in_sizes, int n_in,
                              void* d_out, int out_size)
{
    const float* q    = (const float*)d_in[0];
    const float* k    = (const float*)d_in[1];
    const float* v    = (const float*)d_in[2];
    const float* mask = (const float*)d_in[3];
    const float* Wq   = (const float*)d_in[4];
    const float* Wk   = (const float*)d_in[5];
    const float* Wv   = (const float*)d_in[6];
    const float* Wf   = (const float*)d_in[7];
    float* out = (float*)d_out;

    const int proj_smem = (128 * 76 + 64 * 76) * (int)sizeof(float);  // 58368
    const int attn_smem = 19968 * (int)sizeof(float);                 // 79872
    const int gemm_smem = 18432 * (int)sizeof(float);                 // 73728
    cudaFuncSetAttribute(proj_mma_kernel,
                         cudaFuncAttributeMaxDynamicSharedMemorySize, proj_smem);
    cudaFuncSetAttribute(attn_tf32_kernel,
                         cudaFuncAttributeMaxDynamicSharedMemorySize, attn_smem);
    cudaFuncSetAttribute(gemm_tf32_kernel,
                         cudaFuncAttributeMaxDynamicSharedMemorySize, gemm_smem);

    proj_mma_kernel<<<dim3(NN / 128, BB * HH, 4), 256, proj_smem>>>(
        q, k, v, Wq, Wk, Wv, Wf);
    attn_tf32_kernel<<<dim3(NN / 128, BB * HH), 256, attn_smem>>>(mask);
    gemm_tf32_kernel<<<dim3(EE / 128, (BB * NN) / 128), 256, gemm_smem>>>(out);
}

// round 11
// speedup vs baseline: 1.6033x; 1.5553x over previous
#include <cuda_runtime.h>
#include <cuda_fp16.h>
#include <math.h>
#include <stdint.h>

#define BB 16
#define NN 768
#define EE 1024
#define HH 16
#define DD 64
// mask addend in log2 domain: -1e16 * log2(e)
#define NEGV2 (-1.4426950e16f)

// Scratch (static device globals; no runtime allocation allowed). All fp16.
__device__ __half g_qh[BB * HH * NN * DD];   // (B,H,N,D), pre-scaled by log2e/32
__device__ __half g_kh[BB * HH * NN * DD];
__device__ __half g_vh[BB * HH * NN * DD];
__device__ __half g_attn[BB * NN * EE];      // (B,N,E) pre-final-projection
__device__ __half g_wtf[EE * EE];            // fp16 Wf

// ---------------------------------------------------------------------------
// helpers
// ---------------------------------------------------------------------------
__device__ __forceinline__ uint32_t f2tf(float x) {
    uint32_t r;
    asm("cvt.rna.tf32.f32 %0, %1;" : "=r"(r) : "f"(x));
    return r;
}
__device__ __forceinline__ float f2tf_f(float x) {
    return __uint_as_float(f2tf(x));
}
__device__ __forceinline__ float ex2(float x) {
    float y;
    asm("ex2.approx.f32 %0, %1;" : "=f"(y) : "f"(x));
    return y;
}
__device__ __forceinline__ uint32_t pack2(float x, float y) {
    __half2 h = __floats2half2_rn(x, y);
    return *(uint32_t*)&h;
}
__device__ __forceinline__ uint32_t packh(__half x, __half y) {
    __half2 h = __halves2half2(x, y);
    return *(uint32_t*)&h;
}
__device__ __forceinline__ void mma_tf32(float d[4],
                                         uint32_t a0, uint32_t a1, uint32_t a2, uint32_t a3,
                                         uint32_t b0, uint32_t b1) {
    asm volatile(
        "mma.sync.aligned.m16n8k8.row.col.f32.tf32.tf32.f32 "
        "{%0,%1,%2,%3}, {%4,%5,%6,%7}, {%8,%9}, {%0,%1,%2,%3};\n"
        : "+f"(d[0]), "+f"(d[1]), "+f"(d[2]), "+f"(d[3])
        : "r"(a0), "r"(a1), "r"(a2), "r"(a3), "r"(b0), "r"(b1));
}
__device__ __forceinline__ void mma_f16(float d[4],
                                        uint32_t a0, uint32_t a1, uint32_t a2, uint32_t a3,
                                        uint32_t b0, uint32_t b1) {
    asm volatile(
        "mma.sync.aligned.m16n8k16.row.col.f32.f16.f16.f32 "
        "{%0,%1,%2,%3}, {%4,%5,%6,%7}, {%8,%9}, {%0,%1,%2,%3};\n"
        : "+f"(d[0]), "+f"(d[1]), "+f"(d[2]), "+f"(d[3])
        : "r"(a0), "r"(a1), "r"(a2), "r"(a3), "r"(b0), "r"(b1));
}
__device__ __forceinline__ void cp16(void* smem, const void* gmem) {
    uint32_t s = (uint32_t)__cvta_generic_to_shared(smem);
    asm volatile("cp.async.cg.shared.global [%0], [%1], 16;\n" :: "r"(s), "l"(gmem));
}
__device__ __forceinline__ void cp_commit() { asm volatile("cp.async.commit_group;\n"); }
__device__ __forceinline__ void cp_wait0() { asm volatile("cp.async.wait_group 0;\n"); }

// ---------------------------------------------------------------------------
// Stage A (merged): per-head projections (tf32 mma, fp16 output) + Wf->fp16.
// grid (6, 256, 4), block 256.
// Q output scaled by log2e/sqrt(E) so attn softmax uses raw ex2.
// smem (floats): Xs[128][76] | Ws[64][76]  = 58368 B
// ---------------------------------------------------------------------------
#define PXS(r, c_) sm[(r) * 76 + (c_)]
#define PWS(r, c_) sm[9728 + (r) * 76 + (c_)]

__global__ __launch_bounds__(256) void proj_mma_kernel(
    const float* __restrict__ q, const float* __restrict__ k, const float* __restrict__ v,
    const float* __restrict__ Wq, const float* __restrict__ Wk, const float* __restrict__ Wv,
    const float* __restrict__ Wf)
{
    extern __shared__ float sm[];
    const int which = blockIdx.z;
    const int tid = threadIdx.x;

    if (which == 3) {
        // Wf -> fp16, 8 elements per thread (need 131072 threads; grid has 393216)
        const int gid = (blockIdx.y * 6 + blockIdx.x) * 256 + tid;
        if (gid < EE * EE / 8) {
            const float4 v0 = *(const float4*)(Wf + (size_t)gid * 8);
            const float4 v1 = *(const float4*)(Wf + (size_t)gid * 8 + 4);
            __half2 h[4];
            h[0] = __floats2half2_rn(v0.x, v0.y);
            h[1] = __floats2half2_rn(v0.z, v0.w);
            h[2] = __floats2half2_rn(v1.x, v1.y);
            h[3] = __floats2half2_rn(v1.z, v1.w);
            *(float4*)(g_wtf + (size_t)gid * 8) = *(float4*)h;
        }
        return;
    }

    const float* X = (which == 0) ? q : (which == 1) ? k : v;
    const float* W = (which == 0) ? Wq : (which == 1) ? Wk : Wv;
    __half* Y = (which == 0) ? g_qh : (which == 1) ? g_kh : g_vh;
    const float oscl = (which == 0) ? (0.03125f * 1.44269504f) : 1.0f;

    const int bh = blockIdx.y;
    const int b = bh >> 4, h = bh & 15;
    const int n0 = blockIdx.x * 128;

    {
        const int rr = tid >> 4;
        const int c4 = (tid & 15) * 4;
        const float* src = X + ((size_t)b * NN + n0) * EE + h * DD;
        #pragma unroll
        for (int i = 0; i < 8; i++) {
            const int row = rr + 16 * i;
            float4 vv = *(const float4*)(src + (size_t)row * EE + c4);
            *(float4*)&PXS(row, c4) =
                make_float4(f2tf_f(vv.x), f2tf_f(vv.y), f2tf_f(vv.z), f2tf_f(vv.w));
        }
        const float* wsrc = W + h * DD * DD;
        #pragma unroll
        for (int i = 0; i < 4; i++) {
            const int row = rr + 16 * i;
            float4 wv = *(const float4*)(wsrc + row * DD + c4);
            *(float4*)&PWS(row, c4) =
                make_float4(f2tf_f(wv.x), f2tf_f(wv.y), f2tf_f(wv.z), f2tf_f(wv.w));
        }
    }
    __syncthreads();

    const int w = tid >> 5;
    const int lane = tid & 31;
    const int g = lane >> 2;
    const int qd = lane & 3;
    const int qrow = 16 * w + g;

    float acc[8][4] = {};
    #pragma unroll
    for (int kk = 0; kk < 8; kk++) {
        uint32_t a0 = __float_as_uint(PXS(qrow,     kk * 8 + qd));
        uint32_t a1 = __float_as_uint(PXS(qrow + 8, kk * 8 + qd));
        uint32_t a2 = __float_as_uint(PXS(qrow,     kk * 8 + qd + 4));
        uint32_t a3 = __float_as_uint(PXS(qrow + 8, kk * 8 + qd + 4));
        #pragma unroll
        for (int nt = 0; nt < 8; nt++) {
            uint32_t b0 = __float_as_uint(PWS(nt * 8 + g, kk * 8 + qd));
            uint32_t b1 = __float_as_uint(PWS(nt * 8 + g, kk * 8 + qd + 4));
            mma_tf32(acc[nt], a0, a1, a2, a3, b0, b1);
        }
    }

    __half* dst = Y + (((size_t)bh) * NN + n0 + 16 * w) * DD;
    #pragma unroll
    for (int nt = 0; nt < 8; nt++) {
        const int col = nt * 8 + 2 * qd;
        *(__half2*)(dst + (size_t)g * DD + col) =
            __floats2half2_rn(acc[nt][0] * oscl, acc[nt][1] * oscl);
        *(__half2*)(dst + (size_t)(g + 8) * DD + col) =
            __floats2half2_rn(acc[nt][2] * oscl, acc[nt][3] * oscl);
    }
}

// ---------------------------------------------------------------------------
// Stage B: flash attention, fp16 mma m16n8k16, ktile=64 sync staging,
// log2-domain softmax, P fed to PV directly from C-fragments (no shuffles).
// grid (6, 256), block 256, dynamic smem 39936 B, 2 CTAs/SM.
// smem (halves): Qs[128][72] | Ks[64][72] | Vs[64][72] | madd[768] (floats)
// ---------------------------------------------------------------------------
#define QH(r, c_) smh[(r) * 72 + (c_)]
#define KH(r, c_) smh[9216 + (r) * 72 + (c_)]
#define VH(r, c_) smh[13824 + (r) * 72 + (c_)]

__global__ __launch_bounds__(256, 2) void attn_f16_kernel(const float* __restrict__ mask)
{
    extern __shared__ __half smh[];
    float* madd = (float*)(smh + 18432);

    const int bh = blockIdx.y;
    const int b = bh >> 4, h = bh & 15;
    const int q0 = blockIdx.x * 128;
    const int tid = threadIdx.x;
    const int w = tid >> 5;
    const int lane = tid & 31;
    const int g = lane >> 2;
    const int qd = lane & 3;

    for (int i = tid; i < NN; i += 256)
        madd[i] = (mask[h * NN + i] == -INFINITY) ? NEGV2 : 0.f;

    const __half* qb = g_qh + ((size_t)bh * NN + q0) * DD;
    const __half* kb = g_kh + ((size_t)bh * NN) * DD;
    const __half* vb = g_vh + ((size_t)bh * NN) * DD;

    // stage Q (128 rows x 64 halves): 8 threads/row, 4 passes
    {
        const int rr = tid >> 3, c8 = (tid & 7) * 8;
        #pragma unroll
        for (int i = 0; i < 4; i++)
            *(float4*)&QH(rr + 32 * i, c8) =
                *(const float4*)(qb + (size_t)(rr + 32 * i) * DD + c8);
    }
    __syncthreads();

    const int qrow = 16 * w + g;
    const float addq0 = madd[q0 + qrow];
    const float addq1 = madd[q0 + qrow + 8];

    float m0r = -INFINITY, m1r = -INFINITY, l0 = 0.f, l1 = 0.f;
    float o[8][4] = {};

    for (int kt = 0; kt < NN; kt += 64) {
        __syncthreads();
        {
            const int rr = tid >> 3, c8 = (tid & 7) * 8;
            #pragma unroll
            for (int i = 0; i < 2; i++) {
                *(float4*)&KH(rr + 32 * i, c8) =
                    *(const float4*)(kb + (size_t)(kt + rr + 32 * i) * DD + c8);
                *(float4*)&VH(rr + 32 * i, c8) =
                    *(const float4*)(vb + (size_t)(kt + rr + 32 * i) * DD + c8);
            }
        }
        __syncthreads();

        // S = Q K^T  (fp16 m16n8k16)
        float s[8][4] = {};
        #pragma unroll
        for (int kk = 0; kk < 4; kk++) {
            uint32_t a0 = *(uint32_t*)&QH(qrow,     kk * 16 + 2 * qd);
            uint32_t a1 = *(uint32_t*)&QH(qrow + 8, kk * 16 + 2 * qd);
            uint32_t a2 = *(uint32_t*)&QH(qrow,     kk * 16 + 2 * qd + 8);
            uint32_t a3 = *(uint32_t*)&QH(qrow + 8, kk * 16 + 2 * qd + 8);
            #pragma unroll
            for (int nt = 0; nt < 8; nt++) {
                uint32_t b0 = *(uint32_t*)&KH(nt * 8 + g, kk * 16 + 2 * qd);
                uint32_t b1 = *(uint32_t*)&KH(nt * 8 + g, kk * 16 + 2 * qd + 8);
                mma_f16(s[nt], a0, a1, a2, a3, b0, b1);
            }
        }

        // mask + online softmax (log2 domain)
        float pm0 = -INFINITY, pm1 = -INFINITY;
        #pragma unroll
        for (int nt = 0; nt < 8; nt++) {
            float2 mk = *(const float2*)&madd[kt + nt * 8 + 2 * qd];
            s[nt][0] += fmaxf(addq0 + mk.x, NEGV2);
            s[nt][1] += fmaxf(addq0 + mk.y, NEGV2);
            s[nt][2] += fmaxf(addq1 + mk.x, NEGV2);
            s[nt][3] += fmaxf(addq1 + mk.y, NEGV2);
            pm0 = fmaxf(pm0, fmaxf(s[nt][0], s[nt][1]));
            pm1 = fmaxf(pm1, fmaxf(s[nt][2], s[nt][3]));
        }
        pm0 = fmaxf(pm0, __shfl_xor_sync(0xffffffffu, pm0, 1));
        pm0 = fmaxf(pm0, __shfl_xor_sync(0xffffffffu, pm0, 2));
        pm1 = fmaxf(pm1, __shfl_xor_sync(0xffffffffu, pm1, 1));
        pm1 = fmaxf(pm1, __shfl_xor_sync(0xffffffffu, pm1, 2));

        const float mn0 = fmaxf(m0r, pm0), mn1 = fmaxf(m1r, pm1);
        const float corr0 = ex2(m0r - mn0), corr1 = ex2(m1r - mn1);
        m0r = mn0; m1r = mn1;

        float rs0 = 0.f, rs1 = 0.f;
        #pragma unroll
        for (int nt = 0; nt < 8; nt++) {
            s[nt][0] = ex2(s[nt][0] - mn0); rs0 += s[nt][0];
            s[nt][1] = ex2(s[nt][1] - mn0); rs0 += s[nt][1];
            s[nt][2] = ex2(s[nt][2] - mn1); rs1 += s[nt][2];
            s[nt][3] = ex2(s[nt][3] - mn1); rs1 += s[nt][3];
        }
        rs0 += __shfl_xor_sync(0xffffffffu, rs0, 1);
        rs0 += __shfl_xor_sync(0xffffffffu, rs0, 2);
        rs1 += __shfl_xor_sync(0xffffffffu, rs1, 1);
        rs1 += __shfl_xor_sync(0xffffffffu, rs1, 2);
        l0 = l0 * corr0 + rs0;
        l1 = l1 * corr1 + rs1;

        #pragma unroll
        for (int dt = 0; dt < 8; dt++) {
            o[dt][0] *= corr0; o[dt][1] *= corr0;
            o[dt][2] *= corr1; o[dt][3] *= corr1;
        }

        // pack P C-fragments into A-fragments (no shuffles needed for k16!)
        uint32_t ph[8][2];
        #pragma unroll
        for (int nt = 0; nt < 8; nt++) {
            ph[nt][0] = pack2(s[nt][0], s[nt][1]);   // row g,   cols 8nt+2t,+1
            ph[nt][1] = pack2(s[nt][2], s[nt][3]);   // row g+8
        }

        // O += P V
        #pragma unroll
        for (int kk = 0; kk < 4; kk++) {
            uint32_t a0 = ph[2 * kk][0];
            uint32_t a1 = ph[2 * kk][1];
            uint32_t a2 = ph[2 * kk + 1][0];
            uint32_t a3 = ph[2 * kk + 1][1];
            #pragma unroll
            for (int dt = 0; dt < 8; dt++) {
                uint32_t b0 = packh(VH(kk * 16 + 2 * qd,     dt * 8 + g),
                                    VH(kk * 16 + 2 * qd + 1, dt * 8 + g));
                uint32_t b1 = packh(VH(kk * 16 + 2 * qd + 8, dt * 8 + g),
                                    VH(kk * 16 + 2 * qd + 9, dt * 8 + g));
                mma_f16(o[dt], a0, a1, a2, a3, b0, b1);
            }
        }
    }

    const float inv0 = 1.f / l0, inv1 = 1.f / l1;
    __half* ob = g_attn + ((size_t)b * NN + q0 + 16 * w) * EE + h * DD;
    #pragma unroll
    for (int dt = 0; dt < 8; dt++) {
        const int col = dt * 8 + 2 * qd;
        *(__half2*)(ob + (size_t)g * EE + col) =
            __floats2half2_rn(o[dt][0] * inv0, o[dt][1] * inv0);
        *(__half2*)(ob + (size_t)(g + 8) * EE + col) =
            __floats2half2_rn(o[dt][2] * inv1, o[dt][3] * inv1);
    }
}

// ---------------------------------------------------------------------------
// Stage C: out = g_attn @ Wf^T, fp16 mma m16n8k16. 128x128x64(halves) chunks,
// 2-stage cp.async pipeline. grid (8, 96), block 256, smem 73728 B.
// smem (halves): As[2][128][72] | Ws[2][128][72]
// ---------------------------------------------------------------------------
#define ASH(bf, r, c_) smh[(bf) * 9216 + (r) * 72 + (c_)]
#define WSH(bf, r, c_) smh[18432 + (bf) * 9216 + (r) * 72 + (c_)]

__global__ __launch_bounds__(256, 2) void gemm_f16_kernel(float* __restrict__ out)
{
    extern __shared__ __half smh[];

    const int e0 = blockIdx.x * 128;
    const int m0 = blockIdx.y * 128;
    const int tid = threadIdx.x;
    const int w = tid >> 5;
    const int lane = tid & 31;
    const int g = lane >> 2, qd = lane & 3;
    const int mb = (w & 1) * 64;
    const int nb = (w >> 1) * 32;

    const __half* Ab = g_attn + (size_t)m0 * EE;
    const __half* Wb = g_wtf + (size_t)e0 * EE;

    const int rr = tid >> 3;           // 0..31
    const int c8 = (tid & 7) * 8;      // half col of 16B piece

    float acc[4][4][4] = {};

    #pragma unroll
    for (int i = 0; i < 4; i++) {
        cp16(&ASH(0, rr + 32 * i, c8), Ab + (size_t)(rr + 32 * i) * EE + c8);
        cp16(&WSH(0, rr + 32 * i, c8), Wb + (size_t)(rr + 32 * i) * EE + c8);
    }
    cp_commit();

    for (int it = 0; it < EE / 64; it++) {
        const int buf = it & 1;
        cp_wait0();
        __syncthreads();

        if (it + 1 < EE / 64) {
            const int kc = (it + 1) * 64;
            #pragma unroll
            for (int i = 0; i < 4; i++) {
                cp16(&ASH(buf ^ 1, rr + 32 * i, c8),
                     Ab + (size_t)(rr + 32 * i) * EE + kc + c8);
                cp16(&WSH(buf ^ 1, rr + 32 * i, c8),
                     Wb + (size_t)(rr + 32 * i) * EE + kc + c8);
            }
            cp_commit();
        }

        #pragma unroll
        for (int kk = 0; kk < 4; kk++) {
            uint32_t a[4][4];
            #pragma unroll
            for (int mt = 0; mt < 4; mt++) {
                const int row = mb + mt * 16 + g;
                a[mt][0] = *(uint32_t*)&ASH(buf, row,     kk * 16 + 2 * qd);
                a[mt][1] = *(uint32_t*)&ASH(buf, row + 8, kk * 16 + 2 * qd);
                a[mt][2] = *(uint32_t*)&ASH(buf, row,     kk * 16 + 2 * qd + 8);
                a[mt][3] = *(uint32_t*)&ASH(buf, row + 8, kk * 16 + 2 * qd + 8);
            }
            #pragma unroll
            for (int nt = 0; nt < 4; nt++) {
                uint32_t b0 = *(uint32_t*)&WSH(buf, nb + nt * 8 + g, kk * 16 + 2 * qd);
                uint32_t b1 = *(uint32_t*)&WSH(buf, nb + nt * 8 + g, kk * 16 + 2 * qd + 8);
                #pragma unroll
                for (int mt = 0; mt < 4; mt++)
                    mma_f16(acc[mt][nt], a[mt][0], a[mt][1], a[mt][2], a[mt][3], b0, b1);
            }
        }
    }

    #pragma unroll
    for (int mt = 0; mt < 4; mt++) {
        const int row0 = m0 + mb + mt * 16 + g;
        #pragma unroll
        for (int nt = 0; nt < 4; nt++) {
            const int col = e0 + nb + nt * 8 + 2 * qd;
            *(float2*)(out + (size_t)row0 * EE + col) =
                make_float2(acc[mt][nt][0], acc[mt][nt][1]);
            *(float2*)(out + (size_t)(row0 + 8) * EE + col) =
                make_float2(acc[mt][nt][2], acc[mt][nt][3]);
        }
    }
}

// ---------------------------------------------------------------------------
extern "C" void kernel_launch(void* const* d_in, const int* in_sizes, int n_in,
                              void* d_out, int out_size)
{
    const float* q    = (const float*)d_in[0];
    const float* k    = (const float*)d_in[1];
    const float* v    = (const float*)d_in[2];
    const float* mask = (const float*)d_in[3];
    const float* Wq   = (const float*)d_in[4];
    const float* Wk   = (const float*)d_in[5];
    const float* Wv   = (const float*)d_in[6];
    const float* Wf   = (const float*)d_in[7];
    float* out = (float*)d_out;

    const int proj_smem = (128 * 76 + 64 * 76) * (int)sizeof(float);      // 58368
    const int attn_smem = 18432 * 2 + 768 * 4;                            // 39936
    const int gemm_smem = 36864 * 2;                                      // 73728
    cudaFuncSetAttribute(proj_mma_kernel,
                         cudaFuncAttributeMaxDynamicSharedMemorySize, proj_smem);
    cudaFuncSetAttribute(attn_f16_kernel,
                         cudaFuncAttributeMaxDynamicSharedMemorySize, attn_smem);
    cudaFuncSetAttribute(gemm_f16_kernel,
                         cudaFuncAttributeMaxDynamicSharedMemorySize, gemm_smem);

    proj_mma_kernel<<<dim3(NN / 128, BB * HH, 4), 256, proj_smem>>>(
        q, k, v, Wq, Wk, Wv, Wf);
    attn_f16_kernel<<<dim3(NN / 128, BB * HH), 256, attn_smem>>>(mask);
    gemm_f16_kernel<<<dim3(EE / 128, (BB * NN) / 128), 256, gemm_smem>>>(out);
}

// round 12
// speedup vs baseline: 1.6815x; 1.0487x over previous
#include <cuda_runtime.h>
#include <cuda_fp16.h>
#include <math.h>
#include <stdint.h>

#define BB 16
#define NN 768
#define EE 1024
#define HH 16
#define DD 64
// mask addend in log2 domain: -1e16 * log2(e)
#define NEGV2 (-1.4426950e16f)

// Scratch (static device globals; no runtime allocation allowed). All fp16.
__device__ __half g_qh[BB * HH * NN * DD];   // (B,H,N,D), pre-scaled by log2e/32
__device__ __half g_kh[BB * HH * NN * DD];
__device__ __half g_vh[BB * HH * NN * DD];
__device__ __half g_attn[BB * NN * EE];      // (B,N,E) pre-final-projection
__device__ __half g_wtf[EE * EE];            // fp16 Wf

// ---------------------------------------------------------------------------
// helpers
// ---------------------------------------------------------------------------
__device__ __forceinline__ float ex2(float x) {
    float y;
    asm("ex2.approx.f32 %0, %1;" : "=f"(y) : "f"(x));
    return y;
}
__device__ __forceinline__ uint32_t pack2(float x, float y) {
    __half2 h = __floats2half2_rn(x, y);
    return *(uint32_t*)&h;
}
__device__ __forceinline__ uint32_t packh(__half x, __half y) {
    __half2 h = __halves2half2(x, y);
    return *(uint32_t*)&h;
}
__device__ __forceinline__ void mma_f16(float d[4],
                                        uint32_t a0, uint32_t a1, uint32_t a2, uint32_t a3,
                                        uint32_t b0, uint32_t b1) {
    asm volatile(
        "mma.sync.aligned.m16n8k16.row.col.f32.f16.f16.f32 "
        "{%0,%1,%2,%3}, {%4,%5,%6,%7}, {%8,%9}, {%0,%1,%2,%3};\n"
        : "+f"(d[0]), "+f"(d[1]), "+f"(d[2]), "+f"(d[3])
        : "r"(a0), "r"(a1), "r"(a2), "r"(a3), "r"(b0), "r"(b1));
}
__device__ __forceinline__ void cp16(void* smem, const void* gmem) {
    uint32_t s = (uint32_t)__cvta_generic_to_shared(smem);
    asm volatile("cp.async.cg.shared.global [%0], [%1], 16;\n" :: "r"(s), "l"(gmem));
}
__device__ __forceinline__ void cp_commit() { asm volatile("cp.async.commit_group;\n"); }
__device__ __forceinline__ void cp_wait0() { asm volatile("cp.async.wait_group 0;\n"); }

// ---------------------------------------------------------------------------
// Stage A (merged): per-head projections via fp16 mma + Wf->fp16 prepass.
// grid (6, 256, 4), block 256.
// Q output scaled by log2e/sqrt(E) so attn softmax uses raw ex2.
// smem (halves): Xh[128][72] | Wh[64][72]  = 27648 B
// ---------------------------------------------------------------------------
#define PXH(r, c_) psm[(r) * 72 + (c_)]
#define PWH(r, c_) psm[9216 + (r) * 72 + (c_)]

__global__ __launch_bounds__(256) void proj_mma_kernel(
    const float* __restrict__ q, const float* __restrict__ k, const float* __restrict__ v,
    const float* __restrict__ Wq, const float* __restrict__ Wk, const float* __restrict__ Wv,
    const float* __restrict__ Wf)
{
    extern __shared__ __half psm[];
    const int which = blockIdx.z;
    const int tid = threadIdx.x;

    if (which == 3) {
        // Wf -> fp16, 8 elements per thread
        const int gid = (blockIdx.y * 6 + blockIdx.x) * 256 + tid;
        if (gid < EE * EE / 8) {
            const float4 v0 = *(const float4*)(Wf + (size_t)gid * 8);
            const float4 v1 = *(const float4*)(Wf + (size_t)gid * 8 + 4);
            __half2 h[4];
            h[0] = __floats2half2_rn(v0.x, v0.y);
            h[1] = __floats2half2_rn(v0.z, v0.w);
            h[2] = __floats2half2_rn(v1.x, v1.y);
            h[3] = __floats2half2_rn(v1.z, v1.w);
            *(float4*)(g_wtf + (size_t)gid * 8) = *(float4*)h;
        }
        return;
    }

    const float* X = (which == 0) ? q : (which == 1) ? k : v;
    const float* W = (which == 0) ? Wq : (which == 1) ? Wk : Wv;
    __half* Y = (which == 0) ? g_qh : (which == 1) ? g_kh : g_vh;
    const float oscl = (which == 0) ? (0.03125f * 1.44269504f) : 1.0f;

    const int bh = blockIdx.y;
    const int b = bh >> 4, h = bh & 15;
    const int n0 = blockIdx.x * 128;

    // stage X (128x64) and W (64x64) as fp16
    {
        const int rr = tid >> 4;
        const int c4 = (tid & 15) * 4;
        const float* src = X + ((size_t)b * NN + n0) * EE + h * DD;
        #pragma unroll
        for (int i = 0; i < 8; i++) {
            const int row = rr + 16 * i;
            float4 vv = *(const float4*)(src + (size_t)row * EE + c4);
            __half2 h2[2] = {__floats2half2_rn(vv.x, vv.y), __floats2half2_rn(vv.z, vv.w)};
            *(float2*)&PXH(row, c4) = *(float2*)h2;
        }
        const float* wsrc = W + h * DD * DD;
        #pragma unroll
        for (int i = 0; i < 4; i++) {
            const int row = rr + 16 * i;
            float4 wv = *(const float4*)(wsrc + row * DD + c4);
            __half2 h2[2] = {__floats2half2_rn(wv.x, wv.y), __floats2half2_rn(wv.z, wv.w)};
            *(float2*)&PWH(row, c4) = *(float2*)h2;
        }
    }
    __syncthreads();

    const int w = tid >> 5;
    const int lane = tid & 31;
    const int g = lane >> 2;
    const int qd = lane & 3;
    const int qrow = 16 * w + g;

    float acc[8][4] = {};
    #pragma unroll
    for (int kk = 0; kk < 4; kk++) {
        uint32_t a0 = *(uint32_t*)&PXH(qrow,     kk * 16 + 2 * qd);
        uint32_t a1 = *(uint32_t*)&PXH(qrow + 8, kk * 16 + 2 * qd);
        uint32_t a2 = *(uint32_t*)&PXH(qrow,     kk * 16 + 2 * qd + 8);
        uint32_t a3 = *(uint32_t*)&PXH(qrow + 8, kk * 16 + 2 * qd + 8);
        #pragma unroll
        for (int nt = 0; nt < 8; nt++) {
            uint32_t b0 = *(uint32_t*)&PWH(nt * 8 + g, kk * 16 + 2 * qd);
            uint32_t b1 = *(uint32_t*)&PWH(nt * 8 + g, kk * 16 + 2 * qd + 8);
            mma_f16(acc[nt], a0, a1, a2, a3, b0, b1);
        }
    }

    __half* dst = Y + (((size_t)bh) * NN + n0 + 16 * w) * DD;
    #pragma unroll
    for (int nt = 0; nt < 8; nt++) {
        const int col = nt * 8 + 2 * qd;
        *(__half2*)(dst + (size_t)g * DD + col) =
            __floats2half2_rn(acc[nt][0] * oscl, acc[nt][1] * oscl);
        *(__half2*)(dst + (size_t)(g + 8) * DD + col) =
            __floats2half2_rn(acc[nt][2] * oscl, acc[nt][3] * oscl);
    }
}

// ---------------------------------------------------------------------------
// Stage B: flash attention, fp16 mma m16n8k16, ktile=64 sync staging,
// log2-domain softmax with DEFERRED l-reduction (quad-reduce once at end).
// grid (6, 256), block 256, dynamic smem 39936 B, 2 CTAs/SM.
// smem (halves): Qs[128][72] | Ks[64][72] | Vs[64][72] | madd[768] (floats)
// ---------------------------------------------------------------------------
#define QH(r, c_) smh[(r) * 72 + (c_)]
#define KH(r, c_) smh[9216 + (r) * 72 + (c_)]
#define VH(r, c_) smh[13824 + (r) * 72 + (c_)]

__global__ __launch_bounds__(256, 2) void attn_f16_kernel(const float* __restrict__ mask)
{
    extern __shared__ __half smh[];
    float* madd = (float*)(smh + 18432);

    const int bh = blockIdx.y;
    const int b = bh >> 4, h = bh & 15;
    const int q0 = blockIdx.x * 128;
    const int tid = threadIdx.x;
    const int w = tid >> 5;
    const int lane = tid & 31;
    const int g = lane >> 2;
    const int qd = lane & 3;

    for (int i = tid; i < NN; i += 256)
        madd[i] = (mask[h * NN + i] == -INFINITY) ? NEGV2 : 0.f;

    const __half* qb = g_qh + ((size_t)bh * NN + q0) * DD;
    const __half* kb = g_kh + ((size_t)bh * NN) * DD;
    const __half* vb = g_vh + ((size_t)bh * NN) * DD;

    {
        const int rr = tid >> 3, c8 = (tid & 7) * 8;
        #pragma unroll
        for (int i = 0; i < 4; i++)
            *(float4*)&QH(rr + 32 * i, c8) =
                *(const float4*)(qb + (size_t)(rr + 32 * i) * DD + c8);
    }
    __syncthreads();

    const int qrow = 16 * w + g;
    const float addq0 = madd[q0 + qrow];
    const float addq1 = madd[q0 + qrow + 8];

    float m0r = -INFINITY, m1r = -INFINITY;
    float l0 = 0.f, l1 = 0.f;          // PER-THREAD partial sums (reduced at end)
    float o[8][4] = {};

    for (int kt = 0; kt < NN; kt += 64) {
        __syncthreads();
        {
            const int rr = tid >> 3, c8 = (tid & 7) * 8;
            #pragma unroll
            for (int i = 0; i < 2; i++) {
                *(float4*)&KH(rr + 32 * i, c8) =
                    *(const float4*)(kb + (size_t)(kt + rr + 32 * i) * DD + c8);
                *(float4*)&VH(rr + 32 * i, c8) =
                    *(const float4*)(vb + (size_t)(kt + rr + 32 * i) * DD + c8);
            }
        }
        __syncthreads();

        // S = Q K^T
        float s[8][4] = {};
        #pragma unroll
        for (int kk = 0; kk < 4; kk++) {
            uint32_t a0 = *(uint32_t*)&QH(qrow,     kk * 16 + 2 * qd);
            uint32_t a1 = *(uint32_t*)&QH(qrow + 8, kk * 16 + 2 * qd);
            uint32_t a2 = *(uint32_t*)&QH(qrow,     kk * 16 + 2 * qd + 8);
            uint32_t a3 = *(uint32_t*)&QH(qrow + 8, kk * 16 + 2 * qd + 8);
            #pragma unroll
            for (int nt = 0; nt < 8; nt++) {
                uint32_t b0 = *(uint32_t*)&KH(nt * 8 + g, kk * 16 + 2 * qd);
                uint32_t b1 = *(uint32_t*)&KH(nt * 8 + g, kk * 16 + 2 * qd + 8);
                mma_f16(s[nt], a0, a1, a2, a3, b0, b1);
            }
        }

        // mask + online softmax (log2 domain). Max must be quad-uniform.
        float pm0 = -INFINITY, pm1 = -INFINITY;
        #pragma unroll
        for (int nt = 0; nt < 8; nt++) {
            float2 mk = *(const float2*)&madd[kt + nt * 8 + 2 * qd];
            s[nt][0] += fmaxf(addq0 + mk.x, NEGV2);
            s[nt][1] += fmaxf(addq0 + mk.y, NEGV2);
            s[nt][2] += fmaxf(addq1 + mk.x, NEGV2);
            s[nt][3] += fmaxf(addq1 + mk.y, NEGV2);
            pm0 = fmaxf(pm0, fmaxf(s[nt][0], s[nt][1]));
            pm1 = fmaxf(pm1, fmaxf(s[nt][2], s[nt][3]));
        }
        pm0 = fmaxf(pm0, __shfl_xor_sync(0xffffffffu, pm0, 1));
        pm0 = fmaxf(pm0, __shfl_xor_sync(0xffffffffu, pm0, 2));
        pm1 = fmaxf(pm1, __shfl_xor_sync(0xffffffffu, pm1, 1));
        pm1 = fmaxf(pm1, __shfl_xor_sync(0xffffffffu, pm1, 2));

        const float mn0 = fmaxf(m0r, pm0), mn1 = fmaxf(m1r, pm1);
        const float corr0 = ex2(m0r - mn0), corr1 = ex2(m1r - mn1);
        m0r = mn0; m1r = mn1;

        float rs0 = 0.f, rs1 = 0.f;
        #pragma unroll
        for (int nt = 0; nt < 8; nt++) {
            s[nt][0] = ex2(s[nt][0] - mn0); rs0 += s[nt][0];
            s[nt][1] = ex2(s[nt][1] - mn0); rs0 += s[nt][1];
            s[nt][2] = ex2(s[nt][2] - mn1); rs1 += s[nt][2];
            s[nt][3] = ex2(s[nt][3] - mn1); rs1 += s[nt][3];
        }
        // deferred reduction: keep per-thread partials (corr is quad-uniform)
        l0 = l0 * corr0 + rs0;
        l1 = l1 * corr1 + rs1;

        #pragma unroll
        for (int dt = 0; dt < 8; dt++) {
            o[dt][0] *= corr0; o[dt][1] *= corr0;
            o[dt][2] *= corr1; o[dt][3] *= corr1;
        }

        // pack P C-fragments into A-fragments (direct register feed)
        uint32_t ph[8][2];
        #pragma unroll
        for (int nt = 0; nt < 8; nt++) {
            ph[nt][0] = pack2(s[nt][0], s[nt][1]);
            ph[nt][1] = pack2(s[nt][2], s[nt][3]);
        }

        // O += P V
        #pragma unroll
        for (int kk = 0; kk < 4; kk++) {
            uint32_t a0 = ph[2 * kk][0];
            uint32_t a1 = ph[2 * kk][1];
            uint32_t a2 = ph[2 * kk + 1][0];
            uint32_t a3 = ph[2 * kk + 1][1];
            #pragma unroll
            for (int dt = 0; dt < 8; dt++) {
                uint32_t b0 = packh(VH(kk * 16 + 2 * qd,     dt * 8 + g),
                                    VH(kk * 16 + 2 * qd + 1, dt * 8 + g));
                uint32_t b1 = packh(VH(kk * 16 + 2 * qd + 8, dt * 8 + g),
                                    VH(kk * 16 + 2 * qd + 9, dt * 8 + g));
                mma_f16(o[dt], a0, a1, a2, a3, b0, b1);
            }
        }
    }

    // final quad reduction of l partials (once, not per tile)
    l0 += __shfl_xor_sync(0xffffffffu, l0, 1);
    l0 += __shfl_xor_sync(0xffffffffu, l0, 2);
    l1 += __shfl_xor_sync(0xffffffffu, l1, 1);
    l1 += __shfl_xor_sync(0xffffffffu, l1, 2);

    const float inv0 = 1.f / l0, inv1 = 1.f / l1;
    __half* ob = g_attn + ((size_t)b * NN + q0 + 16 * w) * EE + h * DD;
    #pragma unroll
    for (int dt = 0; dt < 8; dt++) {
        const int col = dt * 8 + 2 * qd;
        *(__half2*)(ob + (size_t)g * EE + col) =
            __floats2half2_rn(o[dt][0] * inv0, o[dt][1] * inv0);
        *(__half2*)(ob + (size_t)(g + 8) * EE + col) =
            __floats2half2_rn(o[dt][2] * inv1, o[dt][3] * inv1);
    }
}

// ---------------------------------------------------------------------------
// Stage C: out = g_attn @ Wf^T, fp16 mma m16n8k16. 128x128x64(halves) chunks,
// 2-stage cp.async pipeline. grid (8, 96), block 256, smem 73728 B.
// smem (halves): As[2][128][72] | Ws[2][128][72]
// ---------------------------------------------------------------------------
#define ASH(bf, r, c_) smh[(bf) * 9216 + (r) * 72 + (c_)]
#define WSH(bf, r, c_) smh[18432 + (bf) * 9216 + (r) * 72 + (c_)]

__global__ __launch_bounds__(256, 2) void gemm_f16_kernel(float* __restrict__ out)
{
    extern __shared__ __half smh[];

    const int e0 = blockIdx.x * 128;
    const int m0 = blockIdx.y * 128;
    const int tid = threadIdx.x;
    const int w = tid >> 5;
    const int lane = tid & 31;
    const int g = lane >> 2, qd = lane & 3;
    const int mb = (w & 1) * 64;
    const int nb = (w >> 1) * 32;

    const __half* Ab = g_attn + (size_t)m0 * EE;
    const __half* Wb = g_wtf + (size_t)e0 * EE;

    const int rr = tid >> 3;           // 0..31
    const int c8 = (tid & 7) * 8;      // half col of 16B piece

    float acc[4][4][4] = {};

    #pragma unroll
    for (int i = 0; i < 4; i++) {
        cp16(&ASH(0, rr + 32 * i, c8), Ab + (size_t)(rr + 32 * i) * EE + c8);
        cp16(&WSH(0, rr + 32 * i, c8), Wb + (size_t)(rr + 32 * i) * EE + c8);
    }
    cp_commit();

    for (int it = 0; it < EE / 64; it++) {
        const int buf = it & 1;
        cp_wait0();
        __syncthreads();

        if (it + 1 < EE / 64) {
            const int kc = (it + 1) * 64;
            #pragma unroll
            for (int i = 0; i < 4; i++) {
                cp16(&ASH(buf ^ 1, rr + 32 * i, c8),
                     Ab + (size_t)(rr + 32 * i) * EE + kc + c8);
                cp16(&WSH(buf ^ 1, rr + 32 * i, c8),
                     Wb + (size_t)(rr + 32 * i) * EE + kc + c8);
            }
            cp_commit();
        }

        #pragma unroll
        for (int kk = 0; kk < 4; kk++) {
            uint32_t a[4][4];
            #pragma unroll
            for (int mt = 0; mt < 4; mt++) {
                const int row = mb + mt * 16 + g;
                a[mt][0] = *(uint32_t*)&ASH(buf, row,     kk * 16 + 2 * qd);
                a[mt][1] = *(uint32_t*)&ASH(buf, row + 8, kk * 16 + 2 * qd);
                a[mt][2] = *(uint32_t*)&ASH(buf, row,     kk * 16 + 2 * qd + 8);
                a[mt][3] = *(uint32_t*)&ASH(buf, row + 8, kk * 16 + 2 * qd + 8);
            }
            #pragma unroll
            for (int nt = 0; nt < 4; nt++) {
                uint32_t b0 = *(uint32_t*)&WSH(buf, nb + nt * 8 + g, kk * 16 + 2 * qd);
                uint32_t b1 = *(uint32_t*)&WSH(buf, nb + nt * 8 + g, kk * 16 + 2 * qd + 8);
                #pragma unroll
                for (int mt = 0; mt < 4; mt++)
                    mma_f16(acc[mt][nt], a[mt][0], a[mt][1], a[mt][2], a[mt][3], b0, b1);
            }
        }
    }

    #pragma unroll
    for (int mt = 0; mt < 4; mt++) {
        const int row0 = m0 + mb + mt * 16 + g;
        #pragma unroll
        for (int nt = 0; nt < 4; nt++) {
            const int col = e0 + nb + nt * 8 + 2 * qd;
            *(float2*)(out + (size_t)row0 * EE + col) =
                make_float2(acc[mt][nt][0], acc[mt][nt][1]);
            *(float2*)(out + (size_t)(row0 + 8) * EE + col) =
                make_float2(acc[mt][nt][2], acc[mt][nt][3]);
        }
    }
}

// ---------------------------------------------------------------------------
extern "C" void kernel_launch(void* const* d_in, const int* in_sizes, int n_in,
                              void* d_out, int out_size)
{
    const float* q    = (const float*)d_in[0];
    const float* k    = (const float*)d_in[1];
    const float* v    = (const float*)d_in[2];
    const float* mask = (const float*)d_in[3];
    const float* Wq   = (const float*)d_in[4];
    const float* Wk   = (const float*)d_in[5];
    const float* Wv   = (const float*)d_in[6];
    const float* Wf   = (const float*)d_in[7];
    float* out = (float*)d_out;

    const int proj_smem = (128 * 72 + 64 * 72) * 2;   // 27648
    const int attn_smem = 18432 * 2 + 768 * 4;        // 39936
    const int gemm_smem = 36864 * 2;                  // 73728
    cudaFuncSetAttribute(proj_mma_kernel,
                         cudaFuncAttributeMaxDynamicSharedMemorySize, proj_smem);
    cudaFuncSetAttribute(attn_f16_kernel,
                         cudaFuncAttributeMaxDynamicSharedMemorySize, attn_smem);
    cudaFuncSetAttribute(gemm_f16_kernel,
                         cudaFuncAttributeMaxDynamicSharedMemorySize, gemm_smem);

    proj_mma_kernel<<<dim3(NN / 128, BB * HH, 4), 256, proj_smem>>>(
        q, k, v, Wq, Wk, Wv, Wf);
    attn_f16_kernel<<<dim3(NN / 128, BB * HH), 256, attn_smem>>>(mask);
    gemm_f16_kernel<<<dim3(EE / 128, (BB * NN) / 128), 256, gemm_smem>>>(out);
}

// round 13
// speedup vs baseline: 1.8589x; 1.1055x over previous
#include <cuda_runtime.h>
#include <cuda_fp16.h>
#include <math.h>
#include <stdint.h>

#define BB 16
#define NN 768
#define EE 1024
#define HH 16
#define DD 64
// mask addend in log2 domain: -1e16 * log2(e)
#define NEGV2 (-1.4426950e16f)

// Scratch (static device globals; no runtime allocation allowed). All fp16.
__device__ __half g_qh[BB * HH * NN * DD];   // (B,H,N,D), pre-scaled by log2e/32
__device__ __half g_kh[BB * HH * NN * DD];
__device__ __half g_vh[BB * HH * NN * DD];
__device__ __half g_attn[BB * NN * EE];      // (B,N,E) pre-final-projection
__device__ __half g_wtf[EE * EE];            // fp16 Wf

// ---------------------------------------------------------------------------
// helpers
// ---------------------------------------------------------------------------
__device__ __forceinline__ float ex2(float x) {
    float y;
    asm("ex2.approx.f32 %0, %1;" : "=f"(y) : "f"(x));
    return y;
}
__device__ __forceinline__ uint32_t pack2(float x, float y) {
    __half2 h = __floats2half2_rn(x, y);
    return *(uint32_t*)&h;
}
__device__ __forceinline__ void mma_f16(float d[4],
                                        uint32_t a0, uint32_t a1, uint32_t a2, uint32_t a3,
                                        uint32_t b0, uint32_t b1) {
    asm volatile(
        "mma.sync.aligned.m16n8k16.row.col.f32.f16.f16.f32 "
        "{%0,%1,%2,%3}, {%4,%5,%6,%7}, {%8,%9}, {%0,%1,%2,%3};\n"
        : "+f"(d[0]), "+f"(d[1]), "+f"(d[2]), "+f"(d[3])
        : "r"(a0), "r"(a1), "r"(a2), "r"(a3), "r"(b0), "r"(b1));
}
#define LDSM4T(r0, r1, r2, r3, addr) \
    asm volatile("ldmatrix.sync.aligned.m8n8.x4.trans.shared.b16 {%0,%1,%2,%3}, [%4];" \
                 : "=r"(r0), "=r"(r1), "=r"(r2), "=r"(r3) : "r"(addr))

__device__ __forceinline__ void cp16(void* smem, const void* gmem) {
    uint32_t s = (uint32_t)__cvta_generic_to_shared(smem);
    asm volatile("cp.async.cg.shared.global [%0], [%1], 16;\n" :: "r"(s), "l"(gmem));
}
__device__ __forceinline__ void cp_commit() { asm volatile("cp.async.commit_group;\n"); }
__device__ __forceinline__ void cp_wait0() { asm volatile("cp.async.wait_group 0;\n"); }

// ---------------------------------------------------------------------------
// Stage A (merged): per-head projections via fp16 mma + Wf->fp16 prepass.
// grid (6, 256, 4), block 256.
// Q output scaled by log2e/sqrt(E) so attn softmax uses raw ex2.
// smem (halves): Xh[128][72] | Wh[64][72]  = 27648 B
// ---------------------------------------------------------------------------
#define PXH(r, c_) psm[(r) * 72 + (c_)]
#define PWH(r, c_) psm[9216 + (r) * 72 + (c_)]

__global__ __launch_bounds__(256) void proj_mma_kernel(
    const float* __restrict__ q, const float* __restrict__ k, const float* __restrict__ v,
    const float* __restrict__ Wq, const float* __restrict__ Wk, const float* __restrict__ Wv,
    const float* __restrict__ Wf)
{
    extern __shared__ __half psm[];
    const int which = blockIdx.z;
    const int tid = threadIdx.x;

    if (which == 3) {
        // Wf -> fp16, 8 elements per thread
        const int gid = (blockIdx.y * 6 + blockIdx.x) * 256 + tid;
        if (gid < EE * EE / 8) {
            const float4 v0 = *(const float4*)(Wf + (size_t)gid * 8);
            const float4 v1 = *(const float4*)(Wf + (size_t)gid * 8 + 4);
            __half2 h[4];
            h[0] = __floats2half2_rn(v0.x, v0.y);
            h[1] = __floats2half2_rn(v0.z, v0.w);
            h[2] = __floats2half2_rn(v1.x, v1.y);
            h[3] = __floats2half2_rn(v1.z, v1.w);
            *(float4*)(g_wtf + (size_t)gid * 8) = *(float4*)h;
        }
        return;
    }

    const float* X = (which == 0) ? q : (which == 1) ? k : v;
    const float* W = (which == 0) ? Wq : (which == 1) ? Wk : Wv;
    __half* Y = (which == 0) ? g_qh : (which == 1) ? g_kh : g_vh;
    const float oscl = (which == 0) ? (0.03125f * 1.44269504f) : 1.0f;

    const int bh = blockIdx.y;
    const int b = bh >> 4, h = bh & 15;
    const int n0 = blockIdx.x * 128;

    // stage X (128x64) and W (64x64) as fp16
    {
        const int rr = tid >> 4;
        const int c4 = (tid & 15) * 4;
        const float* src = X + ((size_t)b * NN + n0) * EE + h * DD;
        #pragma unroll
        for (int i = 0; i < 8; i++) {
            const int row = rr + 16 * i;
            float4 vv = *(const float4*)(src + (size_t)row * EE + c4);
            __half2 h2[2] = {__floats2half2_rn(vv.x, vv.y), __floats2half2_rn(vv.z, vv.w)};
            *(float2*)&PXH(row, c4) = *(float2*)h2;
        }
        const float* wsrc = W + h * DD * DD;
        #pragma unroll
        for (int i = 0; i < 4; i++) {
            const int row = rr + 16 * i;
            float4 wv = *(const float4*)(wsrc + row * DD + c4);
            __half2 h2[2] = {__floats2half2_rn(wv.x, wv.y), __floats2half2_rn(wv.z, wv.w)};
            *(float2*)&PWH(row, c4) = *(float2*)h2;
        }
    }
    __syncthreads();

    const int w = tid >> 5;
    const int lane = tid & 31;
    const int g = lane >> 2;
    const int qd = lane & 3;
    const int qrow = 16 * w + g;

    float acc[8][4] = {};
    #pragma unroll
    for (int kk = 0; kk < 4; kk++) {
        uint32_t a0 = *(uint32_t*)&PXH(qrow,     kk * 16 + 2 * qd);
        uint32_t a1 = *(uint32_t*)&PXH(qrow + 8, kk * 16 + 2 * qd);
        uint32_t a2 = *(uint32_t*)&PXH(qrow,     kk * 16 + 2 * qd + 8);
        uint32_t a3 = *(uint32_t*)&PXH(qrow + 8, kk * 16 + 2 * qd + 8);
        #pragma unroll
        for (int nt = 0; nt < 8; nt++) {
            uint32_t b0 = *(uint32_t*)&PWH(nt * 8 + g, kk * 16 + 2 * qd);
            uint32_t b1 = *(uint32_t*)&PWH(nt * 8 + g, kk * 16 + 2 * qd + 8);
            mma_f16(acc[nt], a0, a1, a2, a3, b0, b1);
        }
    }

    __half* dst = Y + (((size_t)bh) * NN + n0 + 16 * w) * DD;
    #pragma unroll
    for (int nt = 0; nt < 8; nt++) {
        const int col = nt * 8 + 2 * qd;
        *(__half2*)(dst + (size_t)g * DD + col) =
            __floats2half2_rn(acc[nt][0] * oscl, acc[nt][1] * oscl);
        *(__half2*)(dst + (size_t)(g + 8) * DD + col) =
            __floats2half2_rn(acc[nt][2] * oscl, acc[nt][3] * oscl);
    }
}

// ---------------------------------------------------------------------------
// Stage B: flash attention, fp16 mma m16n8k16, ktile=64 sync staging,
// log2-domain softmax, deferred l-reduction, V B-frags via ldmatrix.trans.
// grid (6, 256), block 256, dynamic smem 39936 B, 2 CTAs/SM.
// smem (halves): Qs[128][72] | Ks[64][72] | Vs[64][72] | madd[768] (floats)
// ---------------------------------------------------------------------------
#define QH(r, c_) smh[(r) * 72 + (c_)]
#define KH(r, c_) smh[9216 + (r) * 72 + (c_)]
#define VH(r, c_) smh[13824 + (r) * 72 + (c_)]

__global__ __launch_bounds__(256, 2) void attn_f16_kernel(const float* __restrict__ mask)
{
    extern __shared__ __half smh[];
    float* madd = (float*)(smh + 18432);

    const int bh = blockIdx.y;
    const int b = bh >> 4, h = bh & 15;
    const int q0 = blockIdx.x * 128;
    const int tid = threadIdx.x;
    const int w = tid >> 5;
    const int lane = tid & 31;
    const int g = lane >> 2;
    const int qd = lane & 3;

    for (int i = tid; i < NN; i += 256)
        madd[i] = (mask[h * NN + i] == -INFINITY) ? NEGV2 : 0.f;

    const __half* qb = g_qh + ((size_t)bh * NN + q0) * DD;
    const __half* kb = g_kh + ((size_t)bh * NN) * DD;
    const __half* vb = g_vh + ((size_t)bh * NN) * DD;

    {
        const int rr = tid >> 3, c8 = (tid & 7) * 8;
        #pragma unroll
        for (int i = 0; i < 4; i++)
            *(float4*)&QH(rr + 32 * i, c8) =
                *(const float4*)(qb + (size_t)(rr + 32 * i) * DD + c8);
    }
    __syncthreads();

    const int qrow = 16 * w + g;
    const float addq0 = madd[q0 + qrow];
    const float addq1 = madd[q0 + qrow + 8];

    float m0r = -INFINITY, m1r = -INFINITY;
    float l0 = 0.f, l1 = 0.f;          // per-thread partials; reduced at end
    float o[8][4] = {};

    // ldmatrix.trans V address bases: tiles (k-rows x d-cols):
    // lanes 0-7: rows k0-7 @dbase | 8-15: k8-15 @dbase | 16-23: k0-7 @dbase+8
    // | 24-31: k8-15 @dbase+8.  V row stride = 72 halves (conflict-free).
    const uint32_t smbh = (uint32_t)__cvta_generic_to_shared(smh);
    const int sq = lane >> 3, rp = lane & 7;
    uint32_t aV[4];
    #pragma unroll
    for (int dp = 0; dp < 4; dp++)
        aV[dp] = smbh + 2u * (13824 + ((sq & 1) * 8 + rp) * 72
                              + dp * 16 + (sq >> 1) * 8);

    for (int kt = 0; kt < NN; kt += 64) {
        __syncthreads();
        {
            const int rr = tid >> 3, c8 = (tid & 7) * 8;
            #pragma unroll
            for (int i = 0; i < 2; i++) {
                *(float4*)&KH(rr + 32 * i, c8) =
                    *(const float4*)(kb + (size_t)(kt + rr + 32 * i) * DD + c8);
                *(float4*)&VH(rr + 32 * i, c8) =
                    *(const float4*)(vb + (size_t)(kt + rr + 32 * i) * DD + c8);
            }
        }
        __syncthreads();

        // S = Q K^T
        float s[8][4] = {};
        #pragma unroll
        for (int kk = 0; kk < 4; kk++) {
            uint32_t a0 = *(uint32_t*)&QH(qrow,     kk * 16 + 2 * qd);
            uint32_t a1 = *(uint32_t*)&QH(qrow + 8, kk * 16 + 2 * qd);
            uint32_t a2 = *(uint32_t*)&QH(qrow,     kk * 16 + 2 * qd + 8);
            uint32_t a3 = *(uint32_t*)&QH(qrow + 8, kk * 16 + 2 * qd + 8);
            #pragma unroll
            for (int nt = 0; nt < 8; nt++) {
                uint32_t b0 = *(uint32_t*)&KH(nt * 8 + g, kk * 16 + 2 * qd);
                uint32_t b1 = *(uint32_t*)&KH(nt * 8 + g, kk * 16 + 2 * qd + 8);
                mma_f16(s[nt], a0, a1, a2, a3, b0, b1);
            }
        }

        // mask + online softmax (log2 domain); max must be quad-uniform
        float pm0 = -INFINITY, pm1 = -INFINITY;
        #pragma unroll
        for (int nt = 0; nt < 8; nt++) {
            float2 mk = *(const float2*)&madd[kt + nt * 8 + 2 * qd];
            s[nt][0] += fmaxf(addq0 + mk.x, NEGV2);
            s[nt][1] += fmaxf(addq0 + mk.y, NEGV2);
            s[nt][2] += fmaxf(addq1 + mk.x, NEGV2);
            s[nt][3] += fmaxf(addq1 + mk.y, NEGV2);
            pm0 = fmaxf(pm0, fmaxf(s[nt][0], s[nt][1]));
            pm1 = fmaxf(pm1, fmaxf(s[nt][2], s[nt][3]));
        }
        pm0 = fmaxf(pm0, __shfl_xor_sync(0xffffffffu, pm0, 1));
        pm0 = fmaxf(pm0, __shfl_xor_sync(0xffffffffu, pm0, 2));
        pm1 = fmaxf(pm1, __shfl_xor_sync(0xffffffffu, pm1, 1));
        pm1 = fmaxf(pm1, __shfl_xor_sync(0xffffffffu, pm1, 2));

        const float mn0 = fmaxf(m0r, pm0), mn1 = fmaxf(m1r, pm1);
        const float corr0 = ex2(m0r - mn0), corr1 = ex2(m1r - mn1);
        m0r = mn0; m1r = mn1;

        float rs0 = 0.f, rs1 = 0.f;
        #pragma unroll
        for (int nt = 0; nt < 8; nt++) {
            s[nt][0] = ex2(s[nt][0] - mn0); rs0 += s[nt][0];
            s[nt][1] = ex2(s[nt][1] - mn0); rs0 += s[nt][1];
            s[nt][2] = ex2(s[nt][2] - mn1); rs1 += s[nt][2];
            s[nt][3] = ex2(s[nt][3] - mn1); rs1 += s[nt][3];
        }
        l0 = l0 * corr0 + rs0;
        l1 = l1 * corr1 + rs1;

        #pragma unroll
        for (int dt = 0; dt < 8; dt++) {
            o[dt][0] *= corr0; o[dt][1] *= corr0;
            o[dt][2] *= corr1; o[dt][3] *= corr1;
        }

        // pack P C-fragments into A-fragments (direct register feed)
        uint32_t ph[8][2];
        #pragma unroll
        for (int nt = 0; nt < 8; nt++) {
            ph[nt][0] = pack2(s[nt][0], s[nt][1]);
            ph[nt][1] = pack2(s[nt][2], s[nt][3]);
        }

        // O += P V  (V B-fragments via single ldmatrix.x4.trans per 16x16)
        #pragma unroll
        for (int kk = 0; kk < 4; kk++) {
            uint32_t a0 = ph[2 * kk][0];
            uint32_t a1 = ph[2 * kk][1];
            uint32_t a2 = ph[2 * kk + 1][0];
            uint32_t a3 = ph[2 * kk + 1][1];
            #pragma unroll
            for (int dp = 0; dp < 4; dp++) {
                uint32_t b0, b1, b2, b3;
                LDSM4T(b0, b1, b2, b3, aV[dp] + kk * 2304u);
                mma_f16(o[2 * dp],     a0, a1, a2, a3, b0, b1);
                mma_f16(o[2 * dp + 1], a0, a1, a2, a3, b2, b3);
            }
        }
    }

    // final quad reduction of l partials
    l0 += __shfl_xor_sync(0xffffffffu, l0, 1);
    l0 += __shfl_xor_sync(0xffffffffu, l0, 2);
    l1 += __shfl_xor_sync(0xffffffffu, l1, 1);
    l1 += __shfl_xor_sync(0xffffffffu, l1, 2);

    const float inv0 = 1.f / l0, inv1 = 1.f / l1;
    __half* ob = g_attn + ((size_t)b * NN + q0 + 16 * w) * EE + h * DD;
    #pragma unroll
    for (int dt = 0; dt < 8; dt++) {
        const int col = dt * 8 + 2 * qd;
        *(__half2*)(ob + (size_t)g * EE + col) =
            __floats2half2_rn(o[dt][0] * inv0, o[dt][1] * inv0);
        *(__half2*)(ob + (size_t)(g + 8) * EE + col) =
            __floats2half2_rn(o[dt][2] * inv1, o[dt][3] * inv1);
    }
}

// ---------------------------------------------------------------------------
// Stage C: out = g_attn @ Wf^T, fp16 mma m16n8k16. 128x128x64(halves) chunks,
// 2-stage cp.async pipeline. grid (8, 96), block 256, smem 73728 B.
// smem (halves): As[2][128][72] | Ws[2][128][72]
// ---------------------------------------------------------------------------
#define ASH(bf, r, c_) smh[(bf) * 9216 + (r) * 72 + (c_)]
#define WSH(bf, r, c_) smh[18432 + (bf) * 9216 + (r) * 72 + (c_)]

__global__ __launch_bounds__(256, 2) void gemm_f16_kernel(float* __restrict__ out)
{
    extern __shared__ __half smh[];

    const int e0 = blockIdx.x * 128;
    const int m0 = blockIdx.y * 128;
    const int tid = threadIdx.x;
    const int w = tid >> 5;
    const int lane = tid & 31;
    const int g = lane >> 2, qd = lane & 3;
    const int mb = (w & 1) * 64;
    const int nb = (w >> 1) * 32;

    const __half* Ab = g_attn + (size_t)m0 * EE;
    const __half* Wb = g_wtf + (size_t)e0 * EE;

    const int rr = tid >> 3;           // 0..31
    const int c8 = (tid & 7) * 8;      // half col of 16B piece

    float acc[4][4][4] = {};

    #pragma unroll
    for (int i = 0; i < 4; i++) {
        cp16(&ASH(0, rr + 32 * i, c8), Ab + (size_t)(rr + 32 * i) * EE + c8);
        cp16(&WSH(0, rr + 32 * i, c8), Wb + (size_t)(rr + 32 * i) * EE + c8);
    }
    cp_commit();

    for (int it = 0; it < EE / 64; it++) {
        const int buf = it & 1;
        cp_wait0();
        __syncthreads();

        if (it + 1 < EE / 64) {
            const int kc = (it + 1) * 64;
            #pragma unroll
            for (int i = 0; i < 4; i++) {
                cp16(&ASH(buf ^ 1, rr + 32 * i, c8),
                     Ab + (size_t)(rr + 32 * i) * EE + kc + c8);
                cp16(&WSH(buf ^ 1, rr + 32 * i, c8),
                     Wb + (size_t)(rr + 32 * i) * EE + kc + c8);
            }
            cp_commit();
        }

        #pragma unroll
        for (int kk = 0; kk < 4; kk++) {
            uint32_t a[4][4];
            #pragma unroll
            for (int mt = 0; mt < 4; mt++) {
                const int row = mb + mt * 16 + g;
                a[mt][0] = *(uint32_t*)&ASH(buf, row,     kk * 16 + 2 * qd);
                a[mt][1] = *(uint32_t*)&ASH(buf, row + 8, kk * 16 + 2 * qd);
                a[mt][2] = *(uint32_t*)&ASH(buf, row,     kk * 16 + 2 * qd + 8);
                a[mt][3] = *(uint32_t*)&ASH(buf, row + 8, kk * 16 + 2 * qd + 8);
            }
            #pragma unroll
            for (int nt = 0; nt < 4; nt++) {
                uint32_t b0 = *(uint32_t*)&WSH(buf, nb + nt * 8 + g, kk * 16 + 2 * qd);
                uint32_t b1 = *(uint32_t*)&WSH(buf, nb + nt * 8 + g, kk * 16 + 2 * qd + 8);
                #pragma unroll
                for (int mt = 0; mt < 4; mt++)
                    mma_f16(acc[mt][nt], a[mt][0], a[mt][1], a[mt][2], a[mt][3], b0, b1);
            }
        }
    }

    #pragma unroll
    for (int mt = 0; mt < 4; mt++) {
        const int row0 = m0 + mb + mt * 16 + g;
        #pragma unroll
        for (int nt = 0; nt < 4; nt++) {
            const int col = e0 + nb + nt * 8 + 2 * qd;
            *(float2*)(out + (size_t)row0 * EE + col) =
                make_float2(acc[mt][nt][0], acc[mt][nt][1]);
            *(float2*)(out + (size_t)(row0 + 8) * EE + col) =
                make_float2(acc[mt][nt][2], acc[mt][nt][3]);
        }
    }
}

// ---------------------------------------------------------------------------
extern "C" void kernel_launch(void* const* d_in, const int* in_sizes, int n_in,
                              void* d_out, int out_size)
{
    const float* q    = (const float*)d_in[0];
    const float* k    = (const float*)d_in[1];
    const float* v    = (const float*)d_in[2];
    const float* mask = (const float*)d_in[3];
    const float* Wq   = (const float*)d_in[4];
    const float* Wk   = (const float*)d_in[5];
    const float* Wv   = (const float*)d_in[6];
    const float* Wf   = (const float*)d_in[7];
    float* out = (float*)d_out;

    const int proj_smem = (128 * 72 + 64 * 72) * 2;   // 27648
    const int attn_smem = 18432 * 2 + 768 * 4;        // 39936
    const int gemm_smem = 36864 * 2;                  // 73728
    cudaFuncSetAttribute(proj_mma_kernel,
                         cudaFuncAttributeMaxDynamicSharedMemorySize, proj_smem);
    cudaFuncSetAttribute(attn_f16_kernel,
                         cudaFuncAttributeMaxDynamicSharedMemorySize, attn_smem);
    cudaFuncSetAttribute(gemm_f16_kernel,
                         cudaFuncAttributeMaxDynamicSharedMemorySize, gemm_smem);

    proj_mma_kernel<<<dim3(NN / 128, BB * HH, 4), 256, proj_smem>>>(
        q, k, v, Wq, Wk, Wv, Wf);
    attn_f16_kernel<<<dim3(NN / 128, BB * HH), 256, attn_smem>>>(mask);
    gemm_f16_kernel<<<dim3(EE / 128, (BB * NN) / 128), 256, gemm_smem>>>(out);
}